// round 9
// baseline (speedup 1.0000x reference)
#include <cuda_runtime.h>
#include <stdint.h>

#define B_     4
#define CDIM   512
#define LSEQ   2048
#define HEADS_ 8
#define DHEAD  64
#define HID    512
#define O3     1536
#define QSCALE 0.125f

typedef uint32_t u32;

// ------------------------- scratch (device globals) -------------------------
__device__ float    g_qkv[(size_t)B_ * O3 * LSEQ];    // [b][o][l], q pre-scaled
__device__ float    g_att[(size_t)B_ * HID * LSEQ];   // [b][h*64+d][l]
__device__ uint16_t g_qh[(size_t)B_ * HEADS_ * LSEQ * DHEAD]; // [b][h][l][d] bf16
__device__ uint16_t g_ql[(size_t)B_ * HEADS_ * LSEQ * DHEAD];
__device__ uint16_t g_kh[(size_t)B_ * HEADS_ * LSEQ * DHEAD];
__device__ uint16_t g_kl[(size_t)B_ * HEADS_ * LSEQ * DHEAD];
__device__ uint16_t g_vh[(size_t)B_ * HEADS_ * DHEAD * LSEQ]; // [b][h][d][l] fp16

// ------------------------------- helpers -------------------------------------
__device__ __forceinline__ u32 smem_u32(const void* p) {
    u32 a; asm("{ .reg .u64 t; cvta.to.shared.u64 t, %1; cvt.u32.u64 %0, t; }"
               : "=r"(a) : "l"(p));
    return a;
}
__device__ __forceinline__ u32 pack_bf16x2(float a, float b) {   // lo=a, hi=b
    u32 r; asm("cvt.rn.bf16x2.f32 %0, %1, %2;" : "=r"(r) : "f"(b), "f"(a));
    return r;
}
__device__ __forceinline__ u32 pack_f16x2(float a, float b) {    // lo=a, hi=b
    u32 r; asm("cvt.rn.f16x2.f32 %0, %1, %2;" : "=r"(r) : "f"(b), "f"(a));
    return r;
}
__device__ __forceinline__ float bf_lo(u32 w) { return __uint_as_float(w << 16); }
__device__ __forceinline__ float bf_hi(u32 w) { return __uint_as_float(w & 0xffff0000u); }
__device__ __forceinline__ void split_pair(float a, float b, u32& hw, u32& lw) {
    hw = pack_bf16x2(a, b);
    lw = pack_bf16x2(a - bf_lo(hw), b - bf_hi(hw));
}
// bf16 MMA (S path, GEMMs)
__device__ __forceinline__ void mma_bf(float c[4], const u32 a[4], u32 b0, u32 b1) {
    asm volatile(
        "mma.sync.aligned.m16n8k16.row.col.f32.bf16.bf16.f32 "
        "{%0,%1,%2,%3}, {%4,%5,%6,%7}, {%8,%9}, {%0,%1,%2,%3};"
        : "+f"(c[0]), "+f"(c[1]), "+f"(c[2]), "+f"(c[3])
        : "r"(a[0]), "r"(a[1]), "r"(a[2]), "r"(a[3]), "r"(b0), "r"(b1));
}
// fp16 MMA (PV path)
__device__ __forceinline__ void mma_fp(float c[4], const u32 a[4], u32 b0, u32 b1) {
    asm volatile(
        "mma.sync.aligned.m16n8k16.row.col.f32.f16.f16.f32 "
        "{%0,%1,%2,%3}, {%4,%5,%6,%7}, {%8,%9}, {%0,%1,%2,%3};"
        : "+f"(c[0]), "+f"(c[1]), "+f"(c[2]), "+f"(c[3])
        : "r"(a[0]), "r"(a[1]), "r"(a[2]), "r"(a[3]), "r"(b0), "r"(b1));
}
__device__ __forceinline__ void ldsm4(u32 r[4], u32 addr) {
    asm volatile("ldmatrix.sync.aligned.m8n8.x4.shared.b16 {%0,%1,%2,%3}, [%4];"
        : "=r"(r[0]), "=r"(r[1]), "=r"(r[2]), "=r"(r[3]) : "r"(addr));
}
__device__ __forceinline__ void ldsm4t(u32 r[4], u32 addr) {
    asm volatile("ldmatrix.sync.aligned.m8n8.x4.trans.shared.b16 {%0,%1,%2,%3}, [%4];"
        : "=r"(r[0]), "=r"(r[1]), "=r"(r[2]), "=r"(r[3]) : "r"(addr));
}
__device__ __forceinline__ void cp16(u32 dst, const void* src) {
    asm volatile("cp.async.cg.shared.global [%0], [%1], 16;" :: "r"(dst), "l"(src));
}
#define CP_COMMIT() asm volatile("cp.async.commit_group;" ::: "memory")
#define CP_WAIT0()  asm volatile("cp.async.wait_group 0;" ::: "memory")

// ---------------------------------------------------------------------------
// bf16-split GEMM (R5 proven): C[b][m][n] = sum_k A[m][k]*B[b][k][n]
// CTA 128x128, TK=32, 8 warps (4m x 2n); 3-term: AhBh + AhBl + AlBh.
// ---------------------------------------------------------------------------
#define PKA 40
#define PNB 136

__global__ __launch_bounds__(256) void gemm_bf(
    const float* __restrict__ A, const float* __restrict__ Bm,
    float* __restrict__ C, const float* __restrict__ bias,
    int M, int N, int K, long strideB, long strideC, int qrows)
{
    __shared__ uint16_t Ah[128 * PKA], Al[128 * PKA];
    __shared__ uint16_t Bh[32 * PNB],  Bl[32 * PNB];

    const int tid = threadIdx.x;
    const int lane = tid & 31, wid = tid >> 5;
    const int lam = lane & 3;
    const int wm = (wid & 3) * 32, wn = (wid >> 2) * 64;
    const int m0 = blockIdx.y * 128, n0 = blockIdx.x * 128;
    const float* Bb = Bm + (size_t)blockIdx.z * strideB;
    float* Cb = C + (size_t)blockIdx.z * strideC;

    const int ar = tid >> 1, akb = (tid & 1) * 16;
    const int br = tid >> 3, bnb = (tid & 7) * 16;
    const int fr = lane & 15, fc = (lane >> 4) * 8;

    float acc[2][8][4];
#pragma unroll
    for (int mt = 0; mt < 2; mt++)
#pragma unroll
        for (int nt = 0; nt < 8; nt++)
#pragma unroll
            for (int r = 0; r < 4; r++) acc[mt][nt][r] = 0.f;

    for (int k0 = 0; k0 < K; k0 += 32) {
        const float* Ag = A + (size_t)(m0 + ar) * K + k0 + akb;
#pragma unroll
        for (int q = 0; q < 4; q++) {
            float4 v = *(const float4*)(Ag + q * 4);
            u32 h0, l0, h1, l1;
            split_pair(v.x, v.y, h0, l0);
            split_pair(v.z, v.w, h1, l1);
            int kk = akb + q * 4;
            *(u32*)&Ah[ar * PKA + kk]     = h0;
            *(u32*)&Ah[ar * PKA + kk + 2] = h1;
            *(u32*)&Al[ar * PKA + kk]     = l0;
            *(u32*)&Al[ar * PKA + kk + 2] = l1;
        }
        const float* Bg = Bb + (size_t)(k0 + br) * N + n0 + bnb;
#pragma unroll
        for (int q = 0; q < 4; q++) {
            float4 v = *(const float4*)(Bg + q * 4);
            u32 h0, l0, h1, l1;
            split_pair(v.x, v.y, h0, l0);
            split_pair(v.z, v.w, h1, l1);
            int nn = bnb + q * 4;
            *(u32*)&Bh[br * PNB + nn]     = h0;
            *(u32*)&Bh[br * PNB + nn + 2] = h1;
            *(u32*)&Bl[br * PNB + nn]     = l0;
            *(u32*)&Bl[br * PNB + nn + 2] = l1;
        }
        __syncthreads();

#pragma unroll
        for (int ks = 0; ks < 2; ks++) {
            u32 ahf[2][4], alf[2][4];
#pragma unroll
            for (int mt = 0; mt < 2; mt++) {
                u32 off = (u32)((wm + mt * 16 + fr) * PKA + ks * 16 + fc) * 2;
                ldsm4(ahf[mt], smem_u32(Ah) + off);
                ldsm4(alf[mt], smem_u32(Al) + off);
            }
#pragma unroll
            for (int ntp = 0; ntp < 4; ntp++) {
                u32 bhf[4], blf[4];
                u32 off = (u32)((ks * 16 + fr) * PNB + wn + ntp * 16 + fc) * 2;
                ldsm4t(bhf, smem_u32(Bh) + off);
                ldsm4t(blf, smem_u32(Bl) + off);
#pragma unroll
                for (int mt = 0; mt < 2; mt++) {
                    mma_bf(acc[mt][2 * ntp],     ahf[mt], bhf[0], bhf[1]);
                    mma_bf(acc[mt][2 * ntp + 1], ahf[mt], bhf[2], bhf[3]);
                    mma_bf(acc[mt][2 * ntp],     ahf[mt], blf[0], blf[1]);
                    mma_bf(acc[mt][2 * ntp + 1], ahf[mt], blf[2], blf[3]);
                    mma_bf(acc[mt][2 * ntp],     alf[mt], bhf[0], bhf[1]);
                    mma_bf(acc[mt][2 * ntp + 1], alf[mt], bhf[2], bhf[3]);
                }
            }
        }
        __syncthreads();
    }

    const int g = lane >> 2;
#pragma unroll
    for (int mt = 0; mt < 2; mt++) {
#pragma unroll
        for (int r = 0; r < 2; r++) {
            int m = m0 + wm + mt * 16 + g + r * 8;
            float sc = (m < qrows) ? QSCALE : 1.0f;
            float bv = bias ? bias[m] : 0.0f;
            float* Crow = Cb + (size_t)m * N + n0 + wn;
#pragma unroll
            for (int nt = 0; nt < 8; nt++) {
                float2 o;
                o.x = acc[mt][nt][r * 2 + 0] * sc + bv;
                o.y = acc[mt][nt][r * 2 + 1] * sc + bv;
                *(float2*)(Crow + nt * 8 + lam * 2) = o;
            }
        }
    }
}

// ---------------------------------------------------------------------------
// Convert Q/K: qkv fp32 [b][o][l] -> [b][h][l][d] bf16 hi/lo (transpose d,l)
// ---------------------------------------------------------------------------
__global__ __launch_bounds__(256) void conv_qk(const float* __restrict__ qkv)
{
    __shared__ float tile[64][65];
    const int tid = threadIdx.x;
    const int bh = blockIdx.y;
    const int b = bh >> 3, h = bh & 7;
    const int l0 = blockIdx.x * 64;
    const int zb = blockIdx.z * HID;

    const float* src = qkv + ((size_t)b * O3 + zb + h * DHEAD) * LSEQ + l0;
#pragma unroll
    for (int e = tid; e < 4096; e += 256) {
        int d = e >> 6, l = e & 63;
        tile[d][l] = src[(size_t)d * LSEQ + l];
    }
    __syncthreads();

    u32* dh = (u32*)(blockIdx.z ? g_kh : g_qh);
    u32* dl = (u32*)(blockIdx.z ? g_kl : g_ql);
    const size_t rowbase = ((size_t)bh * LSEQ + l0) * 32;
#pragma unroll
    for (int e = tid; e < 2048; e += 256) {
        int l = e >> 5, dp = e & 31;
        float a = tile[dp * 2][l], c = tile[dp * 2 + 1][l];
        u32 hw, lw; split_pair(a, c, hw, lw);
        dh[rowbase + (size_t)l * 32 + dp] = hw;
        dl[rowbase + (size_t)l * 32 + dp] = lw;
    }
}

// V: fp32 -> single fp16, layout copy [b][h][d][l]
__global__ __launch_bounds__(256) void conv_v(const float* __restrict__ qkv)
{
    size_t i4 = (size_t)blockIdx.x * 256 + threadIdx.x;
    size_t i = i4 * 4;
    size_t b = i >> 20, rem = i & ((1u << 20) - 1);
    float4 v = *(const float4*)(qkv + ((size_t)b * O3 + 2 * HID) * LSEQ + rem);
    ((uint2*)g_vh)[i4] = make_uint2(pack_f16x2(v.x, v.y), pack_f16x2(v.z, v.w));
}

// ---------------------------------------------------------------------------
// Flash: cp.async double-buffered K(bf16 hi/lo)/V(fp16); S 3-term bf16,
// PV 1-term fp16. CTA = 128 q of one (b,h); 8 warps x 16 q; key blocks 128.
// ---------------------------------------------------------------------------
#define PD  72
#define PV  136
#define POT 132

#define F_Q   (128 * PD * 2)
#define F_KSZ (128 * PD * 2)
#define F_VSZ (64 * PV * 2)
#define F_STG (2 * F_KSZ + F_VSZ)        // 54272 per stage
#define F_ST0 (2 * F_Q)                  // 36864
#define FLASH_SMEM (F_ST0 + 2 * F_STG)   // 145408

__global__ __launch_bounds__(256, 1) void flash_mma(float* __restrict__ att)
{
    extern __shared__ char smc[];
    const u32 sb = smem_u32(smc);

    const int tid = threadIdx.x;
    const int lane = tid & 31, wid = tid >> 5;
    const int g = lane >> 2, lam = lane & 3;
    const int fr = lane & 15, fc = (lane >> 4) * 8;
    const int bh = blockIdx.y;
    const int q0 = blockIdx.x * 128;

    const uint16_t* kh = g_kh + (size_t)bh * LSEQ * DHEAD;
    const uint16_t* kl = g_kl + (size_t)bh * LSEQ * DHEAD;
    const uint16_t* vh = g_vh + (size_t)bh * DHEAD * LSEQ;

    auto issueKV = [&](int st, int n0) {
        u32 base = sb + F_ST0 + st * F_STG;
#pragma unroll
        for (int j = 0; j < 4; j++) {
            int c = tid * 4 + j;
            int kr = c >> 3, kc = c & 7;
            const size_t koff = (size_t)(n0 + kr) * DHEAD + kc * 8;
            cp16(base + kr * 144 + kc * 16, kh + koff);
            cp16(base + F_KSZ + kr * 144 + kc * 16, kl + koff);
            int vr = c >> 4, vc = c & 15;
            cp16(base + 2 * F_KSZ + vr * 272 + vc * 16,
                 vh + (size_t)vr * LSEQ + n0 + vc * 8);
        }
    };

    issueKV(0, 0);
    CP_COMMIT();

    // stage Q hi/lo
    {
        uint16_t* Qh = (uint16_t*)smc;
        uint16_t* Ql = (uint16_t*)(smc + F_Q);
        const uint16_t* qh = g_qh + ((size_t)bh * LSEQ + q0) * DHEAD;
        const uint16_t* ql = g_ql + ((size_t)bh * LSEQ + q0) * DHEAD;
#pragma unroll
        for (int it = tid; it < 1024; it += 256) {
            int r = it >> 3, c = it & 7;
            *(uint4*)&Qh[r * PD + c * 8] = *(const uint4*)(qh + (size_t)r * 64 + c * 8);
            *(uint4*)&Ql[r * PD + c * 8] = *(const uint4*)(ql + (size_t)r * 64 + c * 8);
        }
    }

    float o[8][4];
#pragma unroll
    for (int nt = 0; nt < 8; nt++)
#pragma unroll
        for (int r = 0; r < 4; r++) o[nt][r] = 0.f;
    float rs0 = 0.f, rs1 = 0.f;

    for (int blk = 0; blk < 16; blk++) {
        CP_WAIT0();
        __syncthreads();
        if (blk < 15) { issueKV((blk + 1) & 1, (blk + 1) * 128); CP_COMMIT(); }

        const u32 kB = sb + F_ST0 + (blk & 1) * F_STG;
        const u32 klB = kB + F_KSZ;
        const u32 vB = kB + 2 * F_KSZ;
        const u32 qB = sb, qlB = sb + F_Q;

        // ---- S = Q K^T (16 q x 128 key), 3-term bf16 split
        float s[16][4];
#pragma unroll
        for (int nt = 0; nt < 16; nt++)
#pragma unroll
            for (int r = 0; r < 4; r++) s[nt][r] = 0.f;

#pragma unroll
        for (int ks = 0; ks < 4; ks++) {
            u32 qhf[4], qlf[4];
            u32 qoff = (u32)((wid * 16 + fr) * PD + ks * 16 + fc) * 2;
            ldsm4(qhf, qB + qoff);
            ldsm4(qlf, qlB + qoff);
#pragma unroll
            for (int ntp = 0; ntp < 8; ntp++) {
                u32 khf[4], klf[4];
                u32 koff = (u32)((ntp * 16 + fr) * PD + ks * 16 + fc) * 2;
                ldsm4(khf, kB + koff);
                ldsm4(klf, klB + koff);
                mma_bf(s[2 * ntp],     qhf, khf[0], khf[2]);
                mma_bf(s[2 * ntp + 1], qhf, khf[1], khf[3]);
                mma_bf(s[2 * ntp],     qhf, klf[0], klf[2]);
                mma_bf(s[2 * ntp + 1], qhf, klf[1], klf[3]);
                mma_bf(s[2 * ntp],     qlf, khf[0], khf[2]);
                mma_bf(s[2 * ntp + 1], qlf, khf[1], khf[3]);
            }
        }

        // ---- exp (no max subtraction) + row sums
#pragma unroll
        for (int nt = 0; nt < 16; nt++) {
            s[nt][0] = __expf(s[nt][0]);
            s[nt][1] = __expf(s[nt][1]);
            s[nt][2] = __expf(s[nt][2]);
            s[nt][3] = __expf(s[nt][3]);
            rs0 += s[nt][0] + s[nt][1];
            rs1 += s[nt][2] + s[nt][3];
        }

        // ---- O += P V : single-term fp16 (11-bit mantissa)
#pragma unroll
        for (int ks2 = 0; ks2 < 8; ks2++) {
            int t = ks2 * 2;
            u32 pa[4];
            pa[0] = pack_f16x2(s[t][0],     s[t][1]);
            pa[1] = pack_f16x2(s[t][2],     s[t][3]);
            pa[2] = pack_f16x2(s[t + 1][0], s[t + 1][1]);
            pa[3] = pack_f16x2(s[t + 1][2], s[t + 1][3]);
#pragma unroll
            for (int dp = 0; dp < 4; dp++) {
                u32 vhf[4];
                u32 voff = (u32)((dp * 16 + fr) * PV + ks2 * 16 + fc) * 2;
                ldsm4(vhf, vB + voff);
                mma_fp(o[2 * dp],     pa, vhf[0], vhf[2]);
                mma_fp(o[2 * dp + 1], pa, vhf[1], vhf[3]);
            }
        }
    }

    // normalize
    rs0 += __shfl_xor_sync(0xffffffffu, rs0, 1);
    rs0 += __shfl_xor_sync(0xffffffffu, rs0, 2);
    rs1 += __shfl_xor_sync(0xffffffffu, rs1, 1);
    rs1 += __shfl_xor_sync(0xffffffffu, rs1, 2);
    const float inv0 = 1.0f / rs0, inv1 = 1.0f / rs1;

    // O^T to smem [d][q], then coalesced fp32 rows
    float* Ot = (float*)(smc + F_ST0);
    __syncthreads();
#pragma unroll
    for (int nt = 0; nt < 8; nt++) {
        int d = nt * 8 + 2 * lam;
        int q = wid * 16 + g;
        Ot[d * POT + q]           = o[nt][0] * inv0;
        Ot[(d + 1) * POT + q]     = o[nt][1] * inv0;
        Ot[d * POT + q + 8]       = o[nt][2] * inv1;
        Ot[(d + 1) * POT + q + 8] = o[nt][3] * inv1;
    }
    __syncthreads();
    const int b = bh >> 3, h = bh & 7;
    float* dst = att + ((size_t)b * HID + h * DHEAD) * LSEQ + q0;
#pragma unroll
    for (int it = tid; it < 2048; it += 256) {
        int d = it >> 5, c = (it & 31) * 4;
        *(float4*)(dst + (size_t)d * LSEQ + c) = *(float4*)&Ot[d * POT + c];
    }
}

// ---------------------------------------------------------------------------
extern "C" void kernel_launch(void* const* d_in, const int* in_sizes, int n_in,
                              void* d_out, int out_size)
{
    const float* x     = (const float*)d_in[0];
    const float* w_qkv = (const float*)d_in[1];
    const float* w_out = (const float*)d_in[2];
    const float* b_out = (const float*)d_in[3];
    float* out = (float*)d_out;

    float *qkv, *att;
    cudaGetSymbolAddress((void**)&qkv, g_qkv);
    cudaGetSymbolAddress((void**)&att, g_att);

    cudaFuncSetAttribute(flash_mma,
        cudaFuncAttributeMaxDynamicSharedMemorySize, FLASH_SMEM);

    dim3 t(256);
    // 1) qkv = w_qkv @ x  (bf16 3-term; q rows scaled)
    gemm_bf<<<dim3(LSEQ / 128, O3 / 128, B_), t>>>(
        w_qkv, x, qkv, nullptr, O3, LSEQ, CDIM,
        (long)CDIM * LSEQ, (long)O3 * LSEQ, HID);

    // 2) flash-layout conversions (Q/K bf16 hi+lo, V fp16)
    conv_qk<<<dim3(LSEQ / 64, B_ * HEADS_, 2), t>>>(qkv);
    conv_v<<<dim3((B_ * HID * LSEQ) / (256 * 4)), t>>>(qkv);

    // 3) flash attention
    flash_mma<<<dim3(LSEQ / 128, B_ * HEADS_), t, FLASH_SMEM>>>(att);

    // 4) out = w_out @ att + b_out
    gemm_bf<<<dim3(LSEQ / 128, CDIM / 128, B_), t>>>(
        w_out, att, out, b_out, CDIM, LSEQ, HID,
        (long)HID * LSEQ, (long)CDIM * LSEQ, 0);
}

// round 10
// speedup vs baseline: 1.6870x; 1.6870x over previous
#include <cuda_runtime.h>
#include <stdint.h>

#define B_     4
#define CDIM   512
#define LSEQ   2048
#define HEADS_ 8
#define DHEAD  64
#define HID    512
#define O3     1536
#define QSCALE 0.125f

typedef uint32_t u32;

// ------------------------- scratch (device globals) -------------------------
__device__ float    g_qkv[(size_t)B_ * O3 * LSEQ];    // [b][o][l], q pre-scaled
__device__ float    g_att[(size_t)B_ * HID * LSEQ];   // [b][h*64+d][l]
__device__ uint16_t g_qh[(size_t)B_ * HEADS_ * LSEQ * DHEAD]; // [b][h][l][d] bf16
__device__ uint16_t g_ql[(size_t)B_ * HEADS_ * LSEQ * DHEAD];
__device__ uint16_t g_kh[(size_t)B_ * HEADS_ * LSEQ * DHEAD];
__device__ uint16_t g_kl[(size_t)B_ * HEADS_ * LSEQ * DHEAD];
__device__ uint16_t g_vh[(size_t)B_ * HEADS_ * DHEAD * LSEQ]; // [b][h][d][l] fp16

// ------------------------------- helpers -------------------------------------
__device__ __forceinline__ u32 smem_u32(const void* p) {
    u32 a; asm("{ .reg .u64 t; cvta.to.shared.u64 t, %1; cvt.u32.u64 %0, t; }"
               : "=r"(a) : "l"(p));
    return a;
}
__device__ __forceinline__ u32 pack_bf16x2(float a, float b) {   // lo=a, hi=b
    u32 r; asm("cvt.rn.bf16x2.f32 %0, %1, %2;" : "=r"(r) : "f"(b), "f"(a));
    return r;
}
__device__ __forceinline__ u32 pack_f16x2(float a, float b) {    // lo=a, hi=b
    u32 r; asm("cvt.rn.f16x2.f32 %0, %1, %2;" : "=r"(r) : "f"(b), "f"(a));
    return r;
}
__device__ __forceinline__ float bf_lo(u32 w) { return __uint_as_float(w << 16); }
__device__ __forceinline__ float bf_hi(u32 w) { return __uint_as_float(w & 0xffff0000u); }
__device__ __forceinline__ void split_pair(float a, float b, u32& hw, u32& lw) {
    hw = pack_bf16x2(a, b);
    lw = pack_bf16x2(a - bf_lo(hw), b - bf_hi(hw));
}
__device__ __forceinline__ void mma_bf(float c[4], const u32 a[4], u32 b0, u32 b1) {
    asm volatile(
        "mma.sync.aligned.m16n8k16.row.col.f32.bf16.bf16.f32 "
        "{%0,%1,%2,%3}, {%4,%5,%6,%7}, {%8,%9}, {%0,%1,%2,%3};"
        : "+f"(c[0]), "+f"(c[1]), "+f"(c[2]), "+f"(c[3])
        : "r"(a[0]), "r"(a[1]), "r"(a[2]), "r"(a[3]), "r"(b0), "r"(b1));
}
__device__ __forceinline__ void mma_fp(float c[4], const u32 a[4], u32 b0, u32 b1) {
    asm volatile(
        "mma.sync.aligned.m16n8k16.row.col.f32.f16.f16.f32 "
        "{%0,%1,%2,%3}, {%4,%5,%6,%7}, {%8,%9}, {%0,%1,%2,%3};"
        : "+f"(c[0]), "+f"(c[1]), "+f"(c[2]), "+f"(c[3])
        : "r"(a[0]), "r"(a[1]), "r"(a[2]), "r"(a[3]), "r"(b0), "r"(b1));
}
__device__ __forceinline__ void ldsm4(u32 r[4], u32 addr) {
    asm volatile("ldmatrix.sync.aligned.m8n8.x4.shared.b16 {%0,%1,%2,%3}, [%4];"
        : "=r"(r[0]), "=r"(r[1]), "=r"(r[2]), "=r"(r[3]) : "r"(addr));
}
__device__ __forceinline__ void ldsm4t(u32 r[4], u32 addr) {
    asm volatile("ldmatrix.sync.aligned.m8n8.x4.trans.shared.b16 {%0,%1,%2,%3}, [%4];"
        : "=r"(r[0]), "=r"(r[1]), "=r"(r[2]), "=r"(r[3]) : "r"(addr));
}

// ---------------------------------------------------------------------------
// bf16-split GEMM (R5 proven): C[b][m][n] = sum_k A[m][k]*B[b][k][n]
// CTA 128x128, TK=32, 8 warps (4m x 2n); 3-term: AhBh + AhBl + AlBh.
// ---------------------------------------------------------------------------
#define PKA 40
#define PNB 136

__global__ __launch_bounds__(256) void gemm_bf(
    const float* __restrict__ A, const float* __restrict__ Bm,
    float* __restrict__ C, const float* __restrict__ bias,
    int M, int N, int K, long strideB, long strideC, int qrows)
{
    __shared__ uint16_t Ah[128 * PKA], Al[128 * PKA];
    __shared__ uint16_t Bh[32 * PNB],  Bl[32 * PNB];

    const int tid = threadIdx.x;
    const int lane = tid & 31, wid = tid >> 5;
    const int lam = lane & 3;
    const int wm = (wid & 3) * 32, wn = (wid >> 2) * 64;
    const int m0 = blockIdx.y * 128, n0 = blockIdx.x * 128;
    const float* Bb = Bm + (size_t)blockIdx.z * strideB;
    float* Cb = C + (size_t)blockIdx.z * strideC;

    const int ar = tid >> 1, akb = (tid & 1) * 16;
    const int br = tid >> 3, bnb = (tid & 7) * 16;
    const int fr = lane & 15, fc = (lane >> 4) * 8;

    float acc[2][8][4];
#pragma unroll
    for (int mt = 0; mt < 2; mt++)
#pragma unroll
        for (int nt = 0; nt < 8; nt++)
#pragma unroll
            for (int r = 0; r < 4; r++) acc[mt][nt][r] = 0.f;

    for (int k0 = 0; k0 < K; k0 += 32) {
        const float* Ag = A + (size_t)(m0 + ar) * K + k0 + akb;
#pragma unroll
        for (int q = 0; q < 4; q++) {
            float4 v = *(const float4*)(Ag + q * 4);
            u32 h0, l0, h1, l1;
            split_pair(v.x, v.y, h0, l0);
            split_pair(v.z, v.w, h1, l1);
            int kk = akb + q * 4;
            *(u32*)&Ah[ar * PKA + kk]     = h0;
            *(u32*)&Ah[ar * PKA + kk + 2] = h1;
            *(u32*)&Al[ar * PKA + kk]     = l0;
            *(u32*)&Al[ar * PKA + kk + 2] = l1;
        }
        const float* Bg = Bb + (size_t)(k0 + br) * N + n0 + bnb;
#pragma unroll
        for (int q = 0; q < 4; q++) {
            float4 v = *(const float4*)(Bg + q * 4);
            u32 h0, l0, h1, l1;
            split_pair(v.x, v.y, h0, l0);
            split_pair(v.z, v.w, h1, l1);
            int nn = bnb + q * 4;
            *(u32*)&Bh[br * PNB + nn]     = h0;
            *(u32*)&Bh[br * PNB + nn + 2] = h1;
            *(u32*)&Bl[br * PNB + nn]     = l0;
            *(u32*)&Bl[br * PNB + nn + 2] = l1;
        }
        __syncthreads();

#pragma unroll
        for (int ks = 0; ks < 2; ks++) {
            u32 ahf[2][4], alf[2][4];
#pragma unroll
            for (int mt = 0; mt < 2; mt++) {
                u32 off = (u32)((wm + mt * 16 + fr) * PKA + ks * 16 + fc) * 2;
                ldsm4(ahf[mt], smem_u32(Ah) + off);
                ldsm4(alf[mt], smem_u32(Al) + off);
            }
#pragma unroll
            for (int ntp = 0; ntp < 4; ntp++) {
                u32 bhf[4], blf[4];
                u32 off = (u32)((ks * 16 + fr) * PNB + wn + ntp * 16 + fc) * 2;
                ldsm4t(bhf, smem_u32(Bh) + off);
                ldsm4t(blf, smem_u32(Bl) + off);
#pragma unroll
                for (int mt = 0; mt < 2; mt++) {
                    mma_bf(acc[mt][2 * ntp],     ahf[mt], bhf[0], bhf[1]);
                    mma_bf(acc[mt][2 * ntp + 1], ahf[mt], bhf[2], bhf[3]);
                    mma_bf(acc[mt][2 * ntp],     ahf[mt], blf[0], blf[1]);
                    mma_bf(acc[mt][2 * ntp + 1], ahf[mt], blf[2], blf[3]);
                    mma_bf(acc[mt][2 * ntp],     alf[mt], bhf[0], bhf[1]);
                    mma_bf(acc[mt][2 * ntp + 1], alf[mt], bhf[2], bhf[3]);
                }
            }
        }
        __syncthreads();
    }

    const int g = lane >> 2;
#pragma unroll
    for (int mt = 0; mt < 2; mt++) {
#pragma unroll
        for (int r = 0; r < 2; r++) {
            int m = m0 + wm + mt * 16 + g + r * 8;
            float sc = (m < qrows) ? QSCALE : 1.0f;
            float bv = bias ? bias[m] : 0.0f;
            float* Crow = Cb + (size_t)m * N + n0 + wn;
#pragma unroll
            for (int nt = 0; nt < 8; nt++) {
                float2 o;
                o.x = acc[mt][nt][r * 2 + 0] * sc + bv;
                o.y = acc[mt][nt][r * 2 + 1] * sc + bv;
                *(float2*)(Crow + nt * 8 + lam * 2) = o;
            }
        }
    }
}

// ---------------------------------------------------------------------------
// Convert Q/K: qkv fp32 [b][o][l] -> [b][h][l][d] bf16 hi/lo (transpose d,l)
// ---------------------------------------------------------------------------
__global__ __launch_bounds__(256) void conv_qk(const float* __restrict__ qkv)
{
    __shared__ float tile[64][65];
    const int tid = threadIdx.x;
    const int bh = blockIdx.y;
    const int b = bh >> 3, h = bh & 7;
    const int l0 = blockIdx.x * 64;
    const int zb = blockIdx.z * HID;

    const float* src = qkv + ((size_t)b * O3 + zb + h * DHEAD) * LSEQ + l0;
#pragma unroll
    for (int e = tid; e < 4096; e += 256) {
        int d = e >> 6, l = e & 63;
        tile[d][l] = src[(size_t)d * LSEQ + l];
    }
    __syncthreads();

    u32* dh = (u32*)(blockIdx.z ? g_kh : g_qh);
    u32* dl = (u32*)(blockIdx.z ? g_kl : g_ql);
    const size_t rowbase = ((size_t)bh * LSEQ + l0) * 32;
#pragma unroll
    for (int e = tid; e < 2048; e += 256) {
        int l = e >> 5, dp = e & 31;
        float a = tile[dp * 2][l], c = tile[dp * 2 + 1][l];
        u32 hw, lw; split_pair(a, c, hw, lw);
        dh[rowbase + (size_t)l * 32 + dp] = hw;
        dl[rowbase + (size_t)l * 32 + dp] = lw;
    }
}

// V: fp32 -> single fp16, layout copy [b][h][d][l]
__global__ __launch_bounds__(256) void conv_v(const float* __restrict__ qkv)
{
    size_t i4 = (size_t)blockIdx.x * 256 + threadIdx.x;
    size_t i = i4 * 4;
    size_t b = i >> 20, rem = i & ((1u << 20) - 1);
    float4 v = *(const float4*)(qkv + ((size_t)b * O3 + 2 * HID) * LSEQ + rem);
    ((uint2*)g_vh)[i4] = make_uint2(pack_f16x2(v.x, v.y), pack_f16x2(v.z, v.w));
}

// ---------------------------------------------------------------------------
// Flash attention v3: 64-key chunks, 2 CTAs/SM (128 regs), plain staging.
// CTA = 128 q of one (b,h); 8 warps x 16 q; S 3-term bf16, PV 1-term fp16.
// No-max softmax: chunk contributions additive; O in registers throughout.
// ---------------------------------------------------------------------------
#define PD  72
#define POT 132

#define F_QH 0
#define F_QL (128 * PD * 2)              // 18432
#define F_KH (2 * 128 * PD * 2)          // 36864
#define F_KL (F_KH + 64 * PD * 2)        // +9216
#define F_V  (F_KH + 2 * 64 * PD * 2)    // +18432
#define FLASH_SMEM (F_KH + 3 * 64 * PD * 2)   // 64512 B -> 2 CTAs/SM

__global__ void __launch_bounds__(256, 2) flash_mma(float* __restrict__ att)
{
    extern __shared__ char smc[];
    uint16_t* Qh = (uint16_t*)(smc + F_QH);
    uint16_t* Ql = (uint16_t*)(smc + F_QL);
    uint16_t* Kh = (uint16_t*)(smc + F_KH);
    uint16_t* Kl = (uint16_t*)(smc + F_KL);
    uint16_t* Vs = (uint16_t*)(smc + F_V);

    const int tid = threadIdx.x;
    const int lane = tid & 31, wid = tid >> 5;
    const int g = lane >> 2, lam = lane & 3;
    const int fr = lane & 15, fc = (lane >> 4) * 8;
    const int bh = blockIdx.y;
    const int q0 = blockIdx.x * 128;

    const uint16_t* kh = g_kh + (size_t)bh * LSEQ * DHEAD;
    const uint16_t* kl = g_kl + (size_t)bh * LSEQ * DHEAD;
    const uint16_t* vh = g_vh + (size_t)bh * DHEAD * LSEQ;

    // stage Q hi/lo [128 q][64 d]
    {
        const uint16_t* qh = g_qh + ((size_t)bh * LSEQ + q0) * DHEAD;
        const uint16_t* ql = g_ql + ((size_t)bh * LSEQ + q0) * DHEAD;
#pragma unroll
        for (int it = tid; it < 1024; it += 256) {
            int r = it >> 3, c = (it & 7) * 8;
            *(uint4*)&Qh[r * PD + c] = *(const uint4*)(qh + (size_t)r * 64 + c);
            *(uint4*)&Ql[r * PD + c] = *(const uint4*)(ql + (size_t)r * 64 + c);
        }
    }

    float o[8][4];
#pragma unroll
    for (int nt = 0; nt < 8; nt++)
#pragma unroll
        for (int r = 0; r < 4; r++) o[nt][r] = 0.f;
    float rs0 = 0.f, rs1 = 0.f;

    const u32 qB = smem_u32(Qh), qlB = smem_u32(Ql);
    const u32 kB = smem_u32(Kh), klB = smem_u32(Kl), vB = smem_u32(Vs);

    for (int n0 = 0; n0 < LSEQ; n0 += 64) {
        __syncthreads();
        // stage K hi/lo [64 key][64 d] and V [64 d][64 key]
#pragma unroll
        for (int it = tid; it < 512; it += 256) {
            int r = it >> 3, c = (it & 7) * 8;
            *(uint4*)&Kh[r * PD + c] =
                *(const uint4*)(kh + (size_t)(n0 + r) * 64 + c);
            *(uint4*)&Kl[r * PD + c] =
                *(const uint4*)(kl + (size_t)(n0 + r) * 64 + c);
            *(uint4*)&Vs[r * PD + c] =
                *(const uint4*)(vh + (size_t)r * LSEQ + n0 + c);
        }
        __syncthreads();

        // ---- S = Q K^T (16 q x 64 key), 3-term bf16 split
        float s[8][4];
#pragma unroll
        for (int nt = 0; nt < 8; nt++)
#pragma unroll
            for (int r = 0; r < 4; r++) s[nt][r] = 0.f;

#pragma unroll
        for (int ks = 0; ks < 4; ks++) {
            u32 qhf[4], qlf[4];
            u32 qoff = (u32)((wid * 16 + fr) * PD + ks * 16 + fc) * 2;
            ldsm4(qhf, qB + qoff);
            ldsm4(qlf, qlB + qoff);
#pragma unroll
            for (int ntp = 0; ntp < 4; ntp++) {
                u32 khf[4], klf[4];
                u32 koff = (u32)((ntp * 16 + fr) * PD + ks * 16 + fc) * 2;
                ldsm4(khf, kB + koff);
                ldsm4(klf, klB + koff);
                mma_bf(s[2 * ntp],     qhf, khf[0], khf[2]);
                mma_bf(s[2 * ntp + 1], qhf, khf[1], khf[3]);
                mma_bf(s[2 * ntp],     qhf, klf[0], klf[2]);
                mma_bf(s[2 * ntp + 1], qhf, klf[1], klf[3]);
                mma_bf(s[2 * ntp],     qlf, khf[0], khf[2]);
                mma_bf(s[2 * ntp + 1], qlf, khf[1], khf[3]);
            }
        }

        // ---- exp (no max subtraction) + row sums
#pragma unroll
        for (int nt = 0; nt < 8; nt++) {
            s[nt][0] = __expf(s[nt][0]);
            s[nt][1] = __expf(s[nt][1]);
            s[nt][2] = __expf(s[nt][2]);
            s[nt][3] = __expf(s[nt][3]);
            rs0 += s[nt][0] + s[nt][1];
            rs1 += s[nt][2] + s[nt][3];
        }

        // ---- O += P V : single-term fp16
#pragma unroll
        for (int ks2 = 0; ks2 < 4; ks2++) {
            int t = ks2 * 2;
            u32 pa[4];
            pa[0] = pack_f16x2(s[t][0],     s[t][1]);
            pa[1] = pack_f16x2(s[t][2],     s[t][3]);
            pa[2] = pack_f16x2(s[t + 1][0], s[t + 1][1]);
            pa[3] = pack_f16x2(s[t + 1][2], s[t + 1][3]);
#pragma unroll
            for (int dp = 0; dp < 4; dp++) {
                u32 vhf[4];
                u32 voff = (u32)((dp * 16 + fr) * PD + ks2 * 16 + fc) * 2;
                ldsm4(vhf, vB + voff);
                mma_fp(o[2 * dp],     pa, vhf[0], vhf[2]);
                mma_fp(o[2 * dp + 1], pa, vhf[1], vhf[3]);
            }
        }
    }

    // normalize (row sums live in the 4 lam lanes of each quad)
    rs0 += __shfl_xor_sync(0xffffffffu, rs0, 1);
    rs0 += __shfl_xor_sync(0xffffffffu, rs0, 2);
    rs1 += __shfl_xor_sync(0xffffffffu, rs1, 1);
    rs1 += __shfl_xor_sync(0xffffffffu, rs1, 2);
    const float inv0 = 1.0f / rs0, inv1 = 1.0f / rs1;

    // O^T staging [64 d][128 q] fp32 in Q region (Q dead now)
    float* Ot = (float*)smc;
    __syncthreads();
#pragma unroll
    for (int nt = 0; nt < 8; nt++) {
        int d = nt * 8 + 2 * lam;
        int q = wid * 16 + g;
        Ot[d * POT + q]           = o[nt][0] * inv0;
        Ot[(d + 1) * POT + q]     = o[nt][1] * inv0;
        Ot[d * POT + q + 8]       = o[nt][2] * inv1;
        Ot[(d + 1) * POT + q + 8] = o[nt][3] * inv1;
    }
    __syncthreads();
    const int b = bh >> 3, h = bh & 7;
    float* dst = att + ((size_t)b * HID + h * DHEAD) * LSEQ + q0;
#pragma unroll
    for (int it = tid; it < 2048; it += 256) {
        int d = it >> 5, c = (it & 31) * 4;
        *(float4*)(dst + (size_t)d * LSEQ + c) = *(float4*)&Ot[d * POT + c];
    }
}

// ---------------------------------------------------------------------------
extern "C" void kernel_launch(void* const* d_in, const int* in_sizes, int n_in,
                              void* d_out, int out_size)
{
    const float* x     = (const float*)d_in[0];
    const float* w_qkv = (const float*)d_in[1];
    const float* w_out = (const float*)d_in[2];
    const float* b_out = (const float*)d_in[3];
    float* out = (float*)d_out;

    float *qkv, *att;
    cudaGetSymbolAddress((void**)&qkv, g_qkv);
    cudaGetSymbolAddress((void**)&att, g_att);

    cudaFuncSetAttribute(flash_mma,
        cudaFuncAttributeMaxDynamicSharedMemorySize, FLASH_SMEM);

    dim3 t(256);
    // 1) qkv = w_qkv @ x  (bf16 3-term; q rows scaled)
    gemm_bf<<<dim3(LSEQ / 128, O3 / 128, B_), t>>>(
        w_qkv, x, qkv, nullptr, O3, LSEQ, CDIM,
        (long)CDIM * LSEQ, (long)O3 * LSEQ, HID);

    // 2) flash-layout conversions (Q/K bf16 hi+lo, V fp16)
    conv_qk<<<dim3(LSEQ / 64, B_ * HEADS_, 2), t>>>(qkv);
    conv_v<<<dim3((B_ * HID * LSEQ) / (256 * 4)), t>>>(qkv);

    // 3) flash attention (2 CTAs/SM)
    flash_mma<<<dim3(LSEQ / 128, B_ * HEADS_), t, FLASH_SMEM>>>(att);

    // 4) out = w_out @ att + b_out
    gemm_bf<<<dim3(LSEQ / 128, CDIM / 128, B_), t>>>(
        w_out, att, out, b_out, CDIM, LSEQ, HID,
        (long)HID * LSEQ, (long)CDIM * LSEQ, 0);
}

// round 11
// speedup vs baseline: 2.1036x; 1.2469x over previous
#include <cuda_runtime.h>
#include <stdint.h>

#define B_     4
#define CDIM   512
#define LSEQ   2048
#define HEADS_ 8
#define DHEAD  64
#define HID    512
#define O3     1536
#define QSCALE 0.125f

typedef uint32_t u32;

// ------------------------- scratch (device globals) -------------------------
__device__ float    g_qkv[(size_t)B_ * O3 * LSEQ];    // [b][o][l], q pre-scaled
__device__ float    g_att[(size_t)B_ * HID * LSEQ];   // [b][h*64+d][l]
__device__ uint16_t g_qh[(size_t)B_ * HEADS_ * LSEQ * DHEAD]; // [b][h][l][d] fp16
__device__ uint16_t g_kh[(size_t)B_ * HEADS_ * LSEQ * DHEAD]; // fp16
__device__ uint16_t g_vh[(size_t)B_ * HEADS_ * DHEAD * LSEQ]; // [b][h][d][l] fp16

// ------------------------------- helpers -------------------------------------
__device__ __forceinline__ u32 smem_u32(const void* p) {
    u32 a; asm("{ .reg .u64 t; cvta.to.shared.u64 t, %1; cvt.u32.u64 %0, t; }"
               : "=r"(a) : "l"(p));
    return a;
}
__device__ __forceinline__ u32 pack_bf16x2(float a, float b) {   // lo=a, hi=b
    u32 r; asm("cvt.rn.bf16x2.f32 %0, %1, %2;" : "=r"(r) : "f"(b), "f"(a));
    return r;
}
__device__ __forceinline__ u32 pack_f16x2(float a, float b) {    // lo=a, hi=b
    u32 r; asm("cvt.rn.f16x2.f32 %0, %1, %2;" : "=r"(r) : "f"(b), "f"(a));
    return r;
}
__device__ __forceinline__ float bf_lo(u32 w) { return __uint_as_float(w << 16); }
__device__ __forceinline__ float bf_hi(u32 w) { return __uint_as_float(w & 0xffff0000u); }
__device__ __forceinline__ void split_pair(float a, float b, u32& hw, u32& lw) {
    hw = pack_bf16x2(a, b);
    lw = pack_bf16x2(a - bf_lo(hw), b - bf_hi(hw));
}
__device__ __forceinline__ void mma_bf(float c[4], const u32 a[4], u32 b0, u32 b1) {
    asm volatile(
        "mma.sync.aligned.m16n8k16.row.col.f32.bf16.bf16.f32 "
        "{%0,%1,%2,%3}, {%4,%5,%6,%7}, {%8,%9}, {%0,%1,%2,%3};"
        : "+f"(c[0]), "+f"(c[1]), "+f"(c[2]), "+f"(c[3])
        : "r"(a[0]), "r"(a[1]), "r"(a[2]), "r"(a[3]), "r"(b0), "r"(b1));
}
__device__ __forceinline__ void mma_fp(float c[4], const u32 a[4], u32 b0, u32 b1) {
    asm volatile(
        "mma.sync.aligned.m16n8k16.row.col.f32.f16.f16.f32 "
        "{%0,%1,%2,%3}, {%4,%5,%6,%7}, {%8,%9}, {%0,%1,%2,%3};"
        : "+f"(c[0]), "+f"(c[1]), "+f"(c[2]), "+f"(c[3])
        : "r"(a[0]), "r"(a[1]), "r"(a[2]), "r"(a[3]), "r"(b0), "r"(b1));
}
__device__ __forceinline__ void ldsm4(u32 r[4], u32 addr) {
    asm volatile("ldmatrix.sync.aligned.m8n8.x4.shared.b16 {%0,%1,%2,%3}, [%4];"
        : "=r"(r[0]), "=r"(r[1]), "=r"(r[2]), "=r"(r[3]) : "r"(addr));
}
__device__ __forceinline__ void ldsm4t(u32 r[4], u32 addr) {
    asm volatile("ldmatrix.sync.aligned.m8n8.x4.trans.shared.b16 {%0,%1,%2,%3}, [%4];"
        : "=r"(r[0]), "=r"(r[1]), "=r"(r[2]), "=r"(r[3]) : "r"(addr));
}

// ---------------------------------------------------------------------------
// bf16-split GEMM (R5 math) + 2 CTAs/SM: C[b][m][n] = sum_k A[m][k]*B[b][k][n]
// CTA 128x128, TK=32, 8 warps (4m x 2n); 3-term: AhBh + AhBl + AlBh.
// ---------------------------------------------------------------------------
#define PKA 40
#define PNB 136

__global__ void __launch_bounds__(256, 2) gemm_bf(
    const float* __restrict__ A, const float* __restrict__ Bm,
    float* __restrict__ C, const float* __restrict__ bias,
    int M, int N, int K, long strideB, long strideC, int qrows)
{
    __shared__ uint16_t Ah[128 * PKA], Al[128 * PKA];
    __shared__ uint16_t Bh[32 * PNB],  Bl[32 * PNB];

    const int tid = threadIdx.x;
    const int lane = tid & 31, wid = tid >> 5;
    const int lam = lane & 3;
    const int wm = (wid & 3) * 32, wn = (wid >> 2) * 64;
    const int m0 = blockIdx.y * 128, n0 = blockIdx.x * 128;
    const float* Bb = Bm + (size_t)blockIdx.z * strideB;
    float* Cb = C + (size_t)blockIdx.z * strideC;

    const int ar = tid >> 1, akb = (tid & 1) * 16;
    const int br = tid >> 3, bnb = (tid & 7) * 16;
    const int fr = lane & 15, fc = (lane >> 4) * 8;

    float acc[2][8][4];
#pragma unroll
    for (int mt = 0; mt < 2; mt++)
#pragma unroll
        for (int nt = 0; nt < 8; nt++)
#pragma unroll
            for (int r = 0; r < 4; r++) acc[mt][nt][r] = 0.f;

    for (int k0 = 0; k0 < K; k0 += 32) {
        const float* Ag = A + (size_t)(m0 + ar) * K + k0 + akb;
#pragma unroll
        for (int q = 0; q < 4; q++) {
            float4 v = *(const float4*)(Ag + q * 4);
            u32 h0, l0, h1, l1;
            split_pair(v.x, v.y, h0, l0);
            split_pair(v.z, v.w, h1, l1);
            int kk = akb + q * 4;
            *(u32*)&Ah[ar * PKA + kk]     = h0;
            *(u32*)&Ah[ar * PKA + kk + 2] = h1;
            *(u32*)&Al[ar * PKA + kk]     = l0;
            *(u32*)&Al[ar * PKA + kk + 2] = l1;
        }
        const float* Bg = Bb + (size_t)(k0 + br) * N + n0 + bnb;
#pragma unroll
        for (int q = 0; q < 4; q++) {
            float4 v = *(const float4*)(Bg + q * 4);
            u32 h0, l0, h1, l1;
            split_pair(v.x, v.y, h0, l0);
            split_pair(v.z, v.w, h1, l1);
            int nn = bnb + q * 4;
            *(u32*)&Bh[br * PNB + nn]     = h0;
            *(u32*)&Bh[br * PNB + nn + 2] = h1;
            *(u32*)&Bl[br * PNB + nn]     = l0;
            *(u32*)&Bl[br * PNB + nn + 2] = l1;
        }
        __syncthreads();

#pragma unroll
        for (int ks = 0; ks < 2; ks++) {
            u32 ahf[2][4], alf[2][4];
#pragma unroll
            for (int mt = 0; mt < 2; mt++) {
                u32 off = (u32)((wm + mt * 16 + fr) * PKA + ks * 16 + fc) * 2;
                ldsm4(ahf[mt], smem_u32(Ah) + off);
                ldsm4(alf[mt], smem_u32(Al) + off);
            }
#pragma unroll
            for (int ntp = 0; ntp < 4; ntp++) {
                u32 bhf[4], blf[4];
                u32 off = (u32)((ks * 16 + fr) * PNB + wn + ntp * 16 + fc) * 2;
                ldsm4t(bhf, smem_u32(Bh) + off);
                ldsm4t(blf, smem_u32(Bl) + off);
#pragma unroll
                for (int mt = 0; mt < 2; mt++) {
                    mma_bf(acc[mt][2 * ntp],     ahf[mt], bhf[0], bhf[1]);
                    mma_bf(acc[mt][2 * ntp + 1], ahf[mt], bhf[2], bhf[3]);
                    mma_bf(acc[mt][2 * ntp],     ahf[mt], blf[0], blf[1]);
                    mma_bf(acc[mt][2 * ntp + 1], ahf[mt], blf[2], blf[3]);
                    mma_bf(acc[mt][2 * ntp],     alf[mt], bhf[0], bhf[1]);
                    mma_bf(acc[mt][2 * ntp + 1], alf[mt], bhf[2], bhf[3]);
                }
            }
        }
        __syncthreads();
    }

    const int g = lane >> 2;
#pragma unroll
    for (int mt = 0; mt < 2; mt++) {
#pragma unroll
        for (int r = 0; r < 2; r++) {
            int m = m0 + wm + mt * 16 + g + r * 8;
            float sc = (m < qrows) ? QSCALE : 1.0f;
            float bv = bias ? bias[m] : 0.0f;
            float* Crow = Cb + (size_t)m * N + n0 + wn;
#pragma unroll
            for (int nt = 0; nt < 8; nt++) {
                float2 o;
                o.x = acc[mt][nt][r * 2 + 0] * sc + bv;
                o.y = acc[mt][nt][r * 2 + 1] * sc + bv;
                *(float2*)(Crow + nt * 8 + lam * 2) = o;
            }
        }
    }
}

// ---------------------------------------------------------------------------
// Convert Q/K: qkv fp32 [b][o][l] -> [b][h][l][d] fp16 (transpose d,l)
// ---------------------------------------------------------------------------
__global__ __launch_bounds__(256) void conv_qk(const float* __restrict__ qkv)
{
    __shared__ float tile[64][65];
    const int tid = threadIdx.x;
    const int bh = blockIdx.y;
    const int b = bh >> 3, h = bh & 7;
    const int l0 = blockIdx.x * 64;
    const int zb = blockIdx.z * HID;

    const float* src = qkv + ((size_t)b * O3 + zb + h * DHEAD) * LSEQ + l0;
#pragma unroll
    for (int e = tid; e < 4096; e += 256) {
        int d = e >> 6, l = e & 63;
        tile[d][l] = src[(size_t)d * LSEQ + l];
    }
    __syncthreads();

    u32* dh = (u32*)(blockIdx.z ? g_kh : g_qh);
    const size_t rowbase = ((size_t)bh * LSEQ + l0) * 32;
#pragma unroll
    for (int e = tid; e < 2048; e += 256) {
        int l = e >> 5, dp = e & 31;
        dh[rowbase + (size_t)l * 32 + dp] =
            pack_f16x2(tile[dp * 2][l], tile[dp * 2 + 1][l]);
    }
}

// V: fp32 -> fp16, layout copy [b][h][d][l]
__global__ __launch_bounds__(256) void conv_v(const float* __restrict__ qkv)
{
    size_t i4 = (size_t)blockIdx.x * 256 + threadIdx.x;
    size_t i = i4 * 4;
    size_t b = i >> 20, rem = i & ((1u << 20) - 1);
    float4 v = *(const float4*)(qkv + ((size_t)b * O3 + 2 * HID) * LSEQ + rem);
    ((uint2*)g_vh)[i4] = make_uint2(pack_f16x2(v.x, v.y), pack_f16x2(v.z, v.w));
}

// ---------------------------------------------------------------------------
// Flash attention v4: all-fp16 single-term MMA paths, 64-key chunks,
// 2 CTAs/SM. CTA = 128 q of one (b,h); 8 warps x 16 q.
// No-max softmax: chunk contributions additive; O in registers throughout.
// ---------------------------------------------------------------------------
#define PD  72
#define POT 132

#define F_QH 0
#define F_KH (128 * PD * 2)              // 18432
#define F_V  (F_KH + 64 * PD * 2)        // +9216
#define FLASH_SMEM (F_V + 64 * PD * 2)   // 36864 B

__global__ void __launch_bounds__(256, 2) flash_mma(float* __restrict__ att)
{
    extern __shared__ char smc[];
    uint16_t* Qh = (uint16_t*)(smc + F_QH);
    uint16_t* Kh = (uint16_t*)(smc + F_KH);
    uint16_t* Vs = (uint16_t*)(smc + F_V);

    const int tid = threadIdx.x;
    const int lane = tid & 31, wid = tid >> 5;
    const int g = lane >> 2, lam = lane & 3;
    const int fr = lane & 15, fc = (lane >> 4) * 8;
    const int bh = blockIdx.y;
    const int q0 = blockIdx.x * 128;

    const uint16_t* kh = g_kh + (size_t)bh * LSEQ * DHEAD;
    const uint16_t* vh = g_vh + (size_t)bh * DHEAD * LSEQ;

    // stage Q [128 q][64 d] fp16
    {
        const uint16_t* qh = g_qh + ((size_t)bh * LSEQ + q0) * DHEAD;
#pragma unroll
        for (int it = tid; it < 1024; it += 256) {
            int r = it >> 3, c = (it & 7) * 8;
            *(uint4*)&Qh[r * PD + c] = *(const uint4*)(qh + (size_t)r * 64 + c);
        }
    }

    float o[8][4];
#pragma unroll
    for (int nt = 0; nt < 8; nt++)
#pragma unroll
        for (int r = 0; r < 4; r++) o[nt][r] = 0.f;
    float rs0 = 0.f, rs1 = 0.f;

    const u32 qB = smem_u32(Qh), kB = smem_u32(Kh), vB = smem_u32(Vs);

    for (int n0 = 0; n0 < LSEQ; n0 += 64) {
        __syncthreads();
        // stage K [64 key][64 d] and V [64 d][64 key] fp16
#pragma unroll
        for (int it = tid; it < 512; it += 256) {
            int r = it >> 3, c = (it & 7) * 8;
            *(uint4*)&Kh[r * PD + c] =
                *(const uint4*)(kh + (size_t)(n0 + r) * 64 + c);
            *(uint4*)&Vs[r * PD + c] =
                *(const uint4*)(vh + (size_t)r * LSEQ + n0 + c);
        }
        __syncthreads();

        // ---- S = Q K^T (16 q x 64 key), single-term fp16
        float s[8][4];
#pragma unroll
        for (int nt = 0; nt < 8; nt++)
#pragma unroll
            for (int r = 0; r < 4; r++) s[nt][r] = 0.f;

#pragma unroll
        for (int ks = 0; ks < 4; ks++) {
            u32 qf[4];
            u32 qoff = (u32)((wid * 16 + fr) * PD + ks * 16 + fc) * 2;
            ldsm4(qf, qB + qoff);
#pragma unroll
            for (int ntp = 0; ntp < 4; ntp++) {
                u32 kf[4];
                u32 koff = (u32)((ntp * 16 + fr) * PD + ks * 16 + fc) * 2;
                ldsm4(kf, kB + koff);
                mma_fp(s[2 * ntp],     qf, kf[0], kf[2]);
                mma_fp(s[2 * ntp + 1], qf, kf[1], kf[3]);
            }
        }

        // ---- exp (no max subtraction) + row sums
#pragma unroll
        for (int nt = 0; nt < 8; nt++) {
            s[nt][0] = __expf(s[nt][0]);
            s[nt][1] = __expf(s[nt][1]);
            s[nt][2] = __expf(s[nt][2]);
            s[nt][3] = __expf(s[nt][3]);
            rs0 += s[nt][0] + s[nt][1];
            rs1 += s[nt][2] + s[nt][3];
        }

        // ---- O += P V : single-term fp16
#pragma unroll
        for (int ks2 = 0; ks2 < 4; ks2++) {
            int t = ks2 * 2;
            u32 pa[4];
            pa[0] = pack_f16x2(s[t][0],     s[t][1]);
            pa[1] = pack_f16x2(s[t][2],     s[t][3]);
            pa[2] = pack_f16x2(s[t + 1][0], s[t + 1][1]);
            pa[3] = pack_f16x2(s[t + 1][2], s[t + 1][3]);
#pragma unroll
            for (int dp = 0; dp < 4; dp++) {
                u32 vf[4];
                u32 voff = (u32)((dp * 16 + fr) * PD + ks2 * 16 + fc) * 2;
                ldsm4(vf, vB + voff);
                mma_fp(o[2 * dp],     pa, vf[0], vf[2]);
                mma_fp(o[2 * dp + 1], pa, vf[1], vf[3]);
            }
        }
    }

    // normalize (row sums live in the 4 lam lanes of each quad)
    rs0 += __shfl_xor_sync(0xffffffffu, rs0, 1);
    rs0 += __shfl_xor_sync(0xffffffffu, rs0, 2);
    rs1 += __shfl_xor_sync(0xffffffffu, rs1, 1);
    rs1 += __shfl_xor_sync(0xffffffffu, rs1, 2);
    const float inv0 = 1.0f / rs0, inv1 = 1.0f / rs1;

    // O^T staging [64 d][128 q] fp32 over all smem (tiles dead now)
    float* Ot = (float*)smc;
    __syncthreads();
#pragma unroll
    for (int nt = 0; nt < 8; nt++) {
        int d = nt * 8 + 2 * lam;
        int q = wid * 16 + g;
        Ot[d * POT + q]           = o[nt][0] * inv0;
        Ot[(d + 1) * POT + q]     = o[nt][1] * inv0;
        Ot[d * POT + q + 8]       = o[nt][2] * inv1;
        Ot[(d + 1) * POT + q + 8] = o[nt][3] * inv1;
    }
    __syncthreads();
    const int b = bh >> 3, h = bh & 7;
    float* dst = att + ((size_t)b * HID + h * DHEAD) * LSEQ + q0;
#pragma unroll
    for (int it = tid; it < 2048; it += 256) {
        int d = it >> 5, c = (it & 31) * 4;
        *(float4*)(dst + (size_t)d * LSEQ + c) = *(float4*)&Ot[d * POT + c];
    }
}

// ---------------------------------------------------------------------------
extern "C" void kernel_launch(void* const* d_in, const int* in_sizes, int n_in,
                              void* d_out, int out_size)
{
    const float* x     = (const float*)d_in[0];
    const float* w_qkv = (const float*)d_in[1];
    const float* w_out = (const float*)d_in[2];
    const float* b_out = (const float*)d_in[3];
    float* out = (float*)d_out;

    float *qkv, *att;
    cudaGetSymbolAddress((void**)&qkv, g_qkv);
    cudaGetSymbolAddress((void**)&att, g_att);

    cudaFuncSetAttribute(flash_mma,
        cudaFuncAttributeMaxDynamicSharedMemorySize, FLASH_SMEM);

    dim3 t(256);
    // 1) qkv = w_qkv @ x  (bf16 3-term; q rows scaled; 2 CTAs/SM)
    gemm_bf<<<dim3(LSEQ / 128, O3 / 128, B_), t>>>(
        w_qkv, x, qkv, nullptr, O3, LSEQ, CDIM,
        (long)CDIM * LSEQ, (long)O3 * LSEQ, HID);

    // 2) flash-layout conversions (Q/K/V fp16)
    conv_qk<<<dim3(LSEQ / 64, B_ * HEADS_, 2), t>>>(qkv);
    conv_v<<<dim3((B_ * HID * LSEQ) / (256 * 4)), t>>>(qkv);

    // 3) flash attention (fp16 paths, 2 CTAs/SM)
    flash_mma<<<dim3(LSEQ / 128, B_ * HEADS_), t, FLASH_SMEM>>>(att);

    // 4) out = w_out @ att + b_out
    gemm_bf<<<dim3(LSEQ / 128, CDIM / 128, B_), t>>>(
        w_out, att, out, b_out, CDIM, LSEQ, HID,
        (long)HID * LSEQ, (long)CDIM * LSEQ, 0);
}

// round 12
// speedup vs baseline: 2.4288x; 1.1546x over previous
#include <cuda_runtime.h>
#include <stdint.h>

#define B_     4
#define CDIM   512
#define LSEQ   2048
#define HEADS_ 8
#define DHEAD  64
#define HID    512
#define O3     1536
#define QSCALE 0.125f

typedef uint32_t u32;

// ------------------------- scratch (device globals) -------------------------
__device__ float    g_qkv[(size_t)B_ * O3 * LSEQ];    // [b][o][l], q pre-scaled
__device__ float    g_att[(size_t)B_ * HID * LSEQ];   // [b][h*64+d][l]
__device__ uint16_t g_qh[(size_t)B_ * HEADS_ * LSEQ * DHEAD]; // [b][h][l][d] fp16
__device__ uint16_t g_kh[(size_t)B_ * HEADS_ * LSEQ * DHEAD]; // fp16
__device__ uint16_t g_vh[(size_t)B_ * HEADS_ * DHEAD * LSEQ]; // [b][h][d][l] fp16

// ------------------------------- helpers -------------------------------------
__device__ __forceinline__ u32 smem_u32(const void* p) {
    u32 a; asm("{ .reg .u64 t; cvta.to.shared.u64 t, %1; cvt.u32.u64 %0, t; }"
               : "=r"(a) : "l"(p));
    return a;
}
__device__ __forceinline__ u32 pack_bf16x2(float a, float b) {   // lo=a, hi=b
    u32 r; asm("cvt.rn.bf16x2.f32 %0, %1, %2;" : "=r"(r) : "f"(b), "f"(a));
    return r;
}
__device__ __forceinline__ u32 pack_f16x2(float a, float b) {    // lo=a, hi=b
    u32 r; asm("cvt.rn.f16x2.f32 %0, %1, %2;" : "=r"(r) : "f"(b), "f"(a));
    return r;
}
__device__ __forceinline__ float bf_lo(u32 w) { return __uint_as_float(w << 16); }
__device__ __forceinline__ float bf_hi(u32 w) { return __uint_as_float(w & 0xffff0000u); }
__device__ __forceinline__ void split_pair(float a, float b, u32& hw, u32& lw) {
    hw = pack_bf16x2(a, b);
    lw = pack_bf16x2(a - bf_lo(hw), b - bf_hi(hw));
}
__device__ __forceinline__ void mma_bf(float c[4], const u32 a[4], u32 b0, u32 b1) {
    asm volatile(
        "mma.sync.aligned.m16n8k16.row.col.f32.bf16.bf16.f32 "
        "{%0,%1,%2,%3}, {%4,%5,%6,%7}, {%8,%9}, {%0,%1,%2,%3};"
        : "+f"(c[0]), "+f"(c[1]), "+f"(c[2]), "+f"(c[3])
        : "r"(a[0]), "r"(a[1]), "r"(a[2]), "r"(a[3]), "r"(b0), "r"(b1));
}
__device__ __forceinline__ void mma_fp(float c[4], const u32 a[4], u32 b0, u32 b1) {
    asm volatile(
        "mma.sync.aligned.m16n8k16.row.col.f32.f16.f16.f32 "
        "{%0,%1,%2,%3}, {%4,%5,%6,%7}, {%8,%9}, {%0,%1,%2,%3};"
        : "+f"(c[0]), "+f"(c[1]), "+f"(c[2]), "+f"(c[3])
        : "r"(a[0]), "r"(a[1]), "r"(a[2]), "r"(a[3]), "r"(b0), "r"(b1));
}
__device__ __forceinline__ void ldsm4(u32 r[4], u32 addr) {
    asm volatile("ldmatrix.sync.aligned.m8n8.x4.shared.b16 {%0,%1,%2,%3}, [%4];"
        : "=r"(r[0]), "=r"(r[1]), "=r"(r[2]), "=r"(r[3]) : "r"(addr));
}
__device__ __forceinline__ void ldsm4t(u32 r[4], u32 addr) {
    asm volatile("ldmatrix.sync.aligned.m8n8.x4.trans.shared.b16 {%0,%1,%2,%3}, [%4];"
        : "=r"(r[0]), "=r"(r[1]), "=r"(r[2]), "=r"(r[3]) : "r"(addr));
}

// ---------------------------------------------------------------------------
// Single-term fp16 GEMM (qkv projection): C[b][m][n] = sum_k A[m][k]*B[b][k][n]
// CTA 128x128, TK=32, 8 warps (4m x 2n). One MMA term: Ah*Bh (fp16).
// ---------------------------------------------------------------------------
#define PKA 40
#define PNB 136

__global__ void __launch_bounds__(256, 2) gemm_fp16(
    const float* __restrict__ A, const float* __restrict__ Bm,
    float* __restrict__ C, int N, int K, long strideB, long strideC, int qrows)
{
    __shared__ uint16_t Ah[128 * PKA];
    __shared__ uint16_t Bh[32 * PNB];

    const int tid = threadIdx.x;
    const int lane = tid & 31, wid = tid >> 5;
    const int lam = lane & 3;
    const int wm = (wid & 3) * 32, wn = (wid >> 2) * 64;
    const int m0 = blockIdx.y * 128, n0 = blockIdx.x * 128;
    const float* Bb = Bm + (size_t)blockIdx.z * strideB;
    float* Cb = C + (size_t)blockIdx.z * strideC;

    const int ar = tid >> 1, akb = (tid & 1) * 16;
    const int br = tid >> 3, bnb = (tid & 7) * 16;
    const int fr = lane & 15, fc = (lane >> 4) * 8;

    float acc[2][8][4];
#pragma unroll
    for (int mt = 0; mt < 2; mt++)
#pragma unroll
        for (int nt = 0; nt < 8; nt++)
#pragma unroll
            for (int r = 0; r < 4; r++) acc[mt][nt][r] = 0.f;

    for (int k0 = 0; k0 < K; k0 += 32) {
        const float* Ag = A + (size_t)(m0 + ar) * K + k0 + akb;
#pragma unroll
        for (int q = 0; q < 4; q++) {
            float4 v = *(const float4*)(Ag + q * 4);
            int kk = akb + q * 4;
            *(u32*)&Ah[ar * PKA + kk]     = pack_f16x2(v.x, v.y);
            *(u32*)&Ah[ar * PKA + kk + 2] = pack_f16x2(v.z, v.w);
        }
        const float* Bg = Bb + (size_t)(k0 + br) * N + n0 + bnb;
#pragma unroll
        for (int q = 0; q < 4; q++) {
            float4 v = *(const float4*)(Bg + q * 4);
            int nn = bnb + q * 4;
            *(u32*)&Bh[br * PNB + nn]     = pack_f16x2(v.x, v.y);
            *(u32*)&Bh[br * PNB + nn + 2] = pack_f16x2(v.z, v.w);
        }
        __syncthreads();

#pragma unroll
        for (int ks = 0; ks < 2; ks++) {
            u32 ahf[2][4];
#pragma unroll
            for (int mt = 0; mt < 2; mt++) {
                u32 off = (u32)((wm + mt * 16 + fr) * PKA + ks * 16 + fc) * 2;
                ldsm4(ahf[mt], smem_u32(Ah) + off);
            }
#pragma unroll
            for (int ntp = 0; ntp < 4; ntp++) {
                u32 bhf[4];
                u32 off = (u32)((ks * 16 + fr) * PNB + wn + ntp * 16 + fc) * 2;
                ldsm4t(bhf, smem_u32(Bh) + off);
#pragma unroll
                for (int mt = 0; mt < 2; mt++) {
                    mma_fp(acc[mt][2 * ntp],     ahf[mt], bhf[0], bhf[1]);
                    mma_fp(acc[mt][2 * ntp + 1], ahf[mt], bhf[2], bhf[3]);
                }
            }
        }
        __syncthreads();
    }

    const int g = lane >> 2;
#pragma unroll
    for (int mt = 0; mt < 2; mt++) {
#pragma unroll
        for (int r = 0; r < 2; r++) {
            int m = m0 + wm + mt * 16 + g + r * 8;
            float sc = (m < qrows) ? QSCALE : 1.0f;
            float* Crow = Cb + (size_t)m * N + n0 + wn;
#pragma unroll
            for (int nt = 0; nt < 8; nt++) {
                float2 o;
                o.x = acc[mt][nt][r * 2 + 0] * sc;
                o.y = acc[mt][nt][r * 2 + 1] * sc;
                *(float2*)(Crow + nt * 8 + lam * 2) = o;
            }
        }
    }
}

// ---------------------------------------------------------------------------
// bf16-split GEMM (3-term, fp32-grade) for the output projection.
// ---------------------------------------------------------------------------
__global__ void __launch_bounds__(256, 2) gemm_bf(
    const float* __restrict__ A, const float* __restrict__ Bm,
    float* __restrict__ C, const float* __restrict__ bias,
    int M, int N, int K, long strideB, long strideC)
{
    __shared__ uint16_t Ah[128 * PKA], Al[128 * PKA];
    __shared__ uint16_t Bh[32 * PNB],  Bl[32 * PNB];

    const int tid = threadIdx.x;
    const int lane = tid & 31, wid = tid >> 5;
    const int lam = lane & 3;
    const int wm = (wid & 3) * 32, wn = (wid >> 2) * 64;
    const int m0 = blockIdx.y * 128, n0 = blockIdx.x * 128;
    const float* Bb = Bm + (size_t)blockIdx.z * strideB;
    float* Cb = C + (size_t)blockIdx.z * strideC;

    const int ar = tid >> 1, akb = (tid & 1) * 16;
    const int br = tid >> 3, bnb = (tid & 7) * 16;
    const int fr = lane & 15, fc = (lane >> 4) * 8;

    float acc[2][8][4];
#pragma unroll
    for (int mt = 0; mt < 2; mt++)
#pragma unroll
        for (int nt = 0; nt < 8; nt++)
#pragma unroll
            for (int r = 0; r < 4; r++) acc[mt][nt][r] = 0.f;

    for (int k0 = 0; k0 < K; k0 += 32) {
        const float* Ag = A + (size_t)(m0 + ar) * K + k0 + akb;
#pragma unroll
        for (int q = 0; q < 4; q++) {
            float4 v = *(const float4*)(Ag + q * 4);
            u32 h0, l0, h1, l1;
            split_pair(v.x, v.y, h0, l0);
            split_pair(v.z, v.w, h1, l1);
            int kk = akb + q * 4;
            *(u32*)&Ah[ar * PKA + kk]     = h0;
            *(u32*)&Ah[ar * PKA + kk + 2] = h1;
            *(u32*)&Al[ar * PKA + kk]     = l0;
            *(u32*)&Al[ar * PKA + kk + 2] = l1;
        }
        const float* Bg = Bb + (size_t)(k0 + br) * N + n0 + bnb;
#pragma unroll
        for (int q = 0; q < 4; q++) {
            float4 v = *(const float4*)(Bg + q * 4);
            u32 h0, l0, h1, l1;
            split_pair(v.x, v.y, h0, l0);
            split_pair(v.z, v.w, h1, l1);
            int nn = bnb + q * 4;
            *(u32*)&Bh[br * PNB + nn]     = h0;
            *(u32*)&Bh[br * PNB + nn + 2] = h1;
            *(u32*)&Bl[br * PNB + nn]     = l0;
            *(u32*)&Bl[br * PNB + nn + 2] = l1;
        }
        __syncthreads();

#pragma unroll
        for (int ks = 0; ks < 2; ks++) {
            u32 ahf[2][4], alf[2][4];
#pragma unroll
            for (int mt = 0; mt < 2; mt++) {
                u32 off = (u32)((wm + mt * 16 + fr) * PKA + ks * 16 + fc) * 2;
                ldsm4(ahf[mt], smem_u32(Ah) + off);
                ldsm4(alf[mt], smem_u32(Al) + off);
            }
#pragma unroll
            for (int ntp = 0; ntp < 4; ntp++) {
                u32 bhf[4], blf[4];
                u32 off = (u32)((ks * 16 + fr) * PNB + wn + ntp * 16 + fc) * 2;
                ldsm4t(bhf, smem_u32(Bh) + off);
                ldsm4t(blf, smem_u32(Bl) + off);
#pragma unroll
                for (int mt = 0; mt < 2; mt++) {
                    mma_bf(acc[mt][2 * ntp],     ahf[mt], bhf[0], bhf[1]);
                    mma_bf(acc[mt][2 * ntp + 1], ahf[mt], bhf[2], bhf[3]);
                    mma_bf(acc[mt][2 * ntp],     ahf[mt], blf[0], blf[1]);
                    mma_bf(acc[mt][2 * ntp + 1], ahf[mt], blf[2], blf[3]);
                    mma_bf(acc[mt][2 * ntp],     alf[mt], bhf[0], bhf[1]);
                    mma_bf(acc[mt][2 * ntp + 1], alf[mt], bhf[2], bhf[3]);
                }
            }
        }
        __syncthreads();
    }

    const int g = lane >> 2;
#pragma unroll
    for (int mt = 0; mt < 2; mt++) {
#pragma unroll
        for (int r = 0; r < 2; r++) {
            int m = m0 + wm + mt * 16 + g + r * 8;
            float bv = bias ? bias[m] : 0.0f;
            float* Crow = Cb + (size_t)m * N + n0 + wn;
#pragma unroll
            for (int nt = 0; nt < 8; nt++) {
                float2 o;
                o.x = acc[mt][nt][r * 2 + 0] + bv;
                o.y = acc[mt][nt][r * 2 + 1] + bv;
                *(float2*)(Crow + nt * 8 + lam * 2) = o;
            }
        }
    }
}

// ---------------------------------------------------------------------------
// Convert Q/K: qkv fp32 [b][o][l] -> [b][h][l][d] fp16 (transpose d,l)
// ---------------------------------------------------------------------------
__global__ __launch_bounds__(256) void conv_qk(const float* __restrict__ qkv)
{
    __shared__ float tile[64][65];
    const int tid = threadIdx.x;
    const int bh = blockIdx.y;
    const int b = bh >> 3, h = bh & 7;
    const int l0 = blockIdx.x * 64;
    const int zb = blockIdx.z * HID;

    const float* src = qkv + ((size_t)b * O3 + zb + h * DHEAD) * LSEQ + l0;
#pragma unroll
    for (int e = tid; e < 4096; e += 256) {
        int d = e >> 6, l = e & 63;
        tile[d][l] = src[(size_t)d * LSEQ + l];
    }
    __syncthreads();

    u32* dh = (u32*)(blockIdx.z ? g_kh : g_qh);
    const size_t rowbase = ((size_t)bh * LSEQ + l0) * 32;
#pragma unroll
    for (int e = tid; e < 2048; e += 256) {
        int l = e >> 5, dp = e & 31;
        dh[rowbase + (size_t)l * 32 + dp] =
            pack_f16x2(tile[dp * 2][l], tile[dp * 2 + 1][l]);
    }
}

// V: fp32 -> fp16, layout copy [b][h][d][l]
__global__ __launch_bounds__(256) void conv_v(const float* __restrict__ qkv)
{
    size_t i4 = (size_t)blockIdx.x * 256 + threadIdx.x;
    size_t i = i4 * 4;
    size_t b = i >> 20, rem = i & ((1u << 20) - 1);
    float4 v = *(const float4*)(qkv + ((size_t)b * O3 + 2 * HID) * LSEQ + rem);
    ((uint2*)g_vh)[i4] = make_uint2(pack_f16x2(v.x, v.y), pack_f16x2(v.z, v.w));
}

// ---------------------------------------------------------------------------
// Flash attention v4 (R11 proven): all-fp16 single-term, 64-key chunks,
// 2 CTAs/SM. CTA = 128 q of one (b,h); 8 warps x 16 q.
// ---------------------------------------------------------------------------
#define PD  72
#define POT 132

#define F_QH 0
#define F_KH (128 * PD * 2)
#define F_V  (F_KH + 64 * PD * 2)
#define FLASH_SMEM (F_V + 64 * PD * 2)   // 36864 B

__global__ void __launch_bounds__(256, 2) flash_mma(float* __restrict__ att)
{
    extern __shared__ char smc[];
    uint16_t* Qh = (uint16_t*)(smc + F_QH);
    uint16_t* Kh = (uint16_t*)(smc + F_KH);
    uint16_t* Vs = (uint16_t*)(smc + F_V);

    const int tid = threadIdx.x;
    const int lane = tid & 31, wid = tid >> 5;
    const int g = lane >> 2, lam = lane & 3;
    const int fr = lane & 15, fc = (lane >> 4) * 8;
    const int bh = blockIdx.y;
    const int q0 = blockIdx.x * 128;

    const uint16_t* kh = g_kh + (size_t)bh * LSEQ * DHEAD;
    const uint16_t* vh = g_vh + (size_t)bh * DHEAD * LSEQ;

    {
        const uint16_t* qh = g_qh + ((size_t)bh * LSEQ + q0) * DHEAD;
#pragma unroll
        for (int it = tid; it < 1024; it += 256) {
            int r = it >> 3, c = (it & 7) * 8;
            *(uint4*)&Qh[r * PD + c] = *(const uint4*)(qh + (size_t)r * 64 + c);
        }
    }

    float o[8][4];
#pragma unroll
    for (int nt = 0; nt < 8; nt++)
#pragma unroll
        for (int r = 0; r < 4; r++) o[nt][r] = 0.f;
    float rs0 = 0.f, rs1 = 0.f;

    const u32 qB = smem_u32(Qh), kB = smem_u32(Kh), vB = smem_u32(Vs);

    for (int n0 = 0; n0 < LSEQ; n0 += 64) {
        __syncthreads();
#pragma unroll
        for (int it = tid; it < 512; it += 256) {
            int r = it >> 3, c = (it & 7) * 8;
            *(uint4*)&Kh[r * PD + c] =
                *(const uint4*)(kh + (size_t)(n0 + r) * 64 + c);
            *(uint4*)&Vs[r * PD + c] =
                *(const uint4*)(vh + (size_t)r * LSEQ + n0 + c);
        }
        __syncthreads();

        float s[8][4];
#pragma unroll
        for (int nt = 0; nt < 8; nt++)
#pragma unroll
            for (int r = 0; r < 4; r++) s[nt][r] = 0.f;

#pragma unroll
        for (int ks = 0; ks < 4; ks++) {
            u32 qf[4];
            u32 qoff = (u32)((wid * 16 + fr) * PD + ks * 16 + fc) * 2;
            ldsm4(qf, qB + qoff);
#pragma unroll
            for (int ntp = 0; ntp < 4; ntp++) {
                u32 kf[4];
                u32 koff = (u32)((ntp * 16 + fr) * PD + ks * 16 + fc) * 2;
                ldsm4(kf, kB + koff);
                mma_fp(s[2 * ntp],     qf, kf[0], kf[2]);
                mma_fp(s[2 * ntp + 1], qf, kf[1], kf[3]);
            }
        }

#pragma unroll
        for (int nt = 0; nt < 8; nt++) {
            s[nt][0] = __expf(s[nt][0]);
            s[nt][1] = __expf(s[nt][1]);
            s[nt][2] = __expf(s[nt][2]);
            s[nt][3] = __expf(s[nt][3]);
            rs0 += s[nt][0] + s[nt][1];
            rs1 += s[nt][2] + s[nt][3];
        }

#pragma unroll
        for (int ks2 = 0; ks2 < 4; ks2++) {
            int t = ks2 * 2;
            u32 pa[4];
            pa[0] = pack_f16x2(s[t][0],     s[t][1]);
            pa[1] = pack_f16x2(s[t][2],     s[t][3]);
            pa[2] = pack_f16x2(s[t + 1][0], s[t + 1][1]);
            pa[3] = pack_f16x2(s[t + 1][2], s[t + 1][3]);
#pragma unroll
            for (int dp = 0; dp < 4; dp++) {
                u32 vf[4];
                u32 voff = (u32)((dp * 16 + fr) * PD + ks2 * 16 + fc) * 2;
                ldsm4(vf, vB + voff);
                mma_fp(o[2 * dp],     pa, vf[0], vf[2]);
                mma_fp(o[2 * dp + 1], pa, vf[1], vf[3]);
            }
        }
    }

    rs0 += __shfl_xor_sync(0xffffffffu, rs0, 1);
    rs0 += __shfl_xor_sync(0xffffffffu, rs0, 2);
    rs1 += __shfl_xor_sync(0xffffffffu, rs1, 1);
    rs1 += __shfl_xor_sync(0xffffffffu, rs1, 2);
    const float inv0 = 1.0f / rs0, inv1 = 1.0f / rs1;

    float* Ot = (float*)smc;
    __syncthreads();
#pragma unroll
    for (int nt = 0; nt < 8; nt++) {
        int d = nt * 8 + 2 * lam;
        int q = wid * 16 + g;
        Ot[d * POT + q]           = o[nt][0] * inv0;
        Ot[(d + 1) * POT + q]     = o[nt][1] * inv0;
        Ot[d * POT + q + 8]       = o[nt][2] * inv1;
        Ot[(d + 1) * POT + q + 8] = o[nt][3] * inv1;
    }
    __syncthreads();
    const int b = bh >> 3, h = bh & 7;
    float* dst = att + ((size_t)b * HID + h * DHEAD) * LSEQ + q0;
#pragma unroll
    for (int it = tid; it < 2048; it += 256) {
        int d = it >> 5, c = (it & 31) * 4;
        *(float4*)(dst + (size_t)d * LSEQ + c) = *(float4*)&Ot[d * POT + c];
    }
}

// ---------------------------------------------------------------------------
extern "C" void kernel_launch(void* const* d_in, const int* in_sizes, int n_in,
                              void* d_out, int out_size)
{
    const float* x     = (const float*)d_in[0];
    const float* w_qkv = (const float*)d_in[1];
    const float* w_out = (const float*)d_in[2];
    const float* b_out = (const float*)d_in[3];
    float* out = (float*)d_out;

    float *qkv, *att;
    cudaGetSymbolAddress((void**)&qkv, g_qkv);
    cudaGetSymbolAddress((void**)&att, g_att);

    cudaFuncSetAttribute(flash_mma,
        cudaFuncAttributeMaxDynamicSharedMemorySize, FLASH_SMEM);

    dim3 t(256);
    // 1) qkv = w_qkv @ x  (single-term fp16; q rows scaled)
    gemm_fp16<<<dim3(LSEQ / 128, O3 / 128, B_), t>>>(
        w_qkv, x, qkv, LSEQ, CDIM,
        (long)CDIM * LSEQ, (long)O3 * LSEQ, HID);

    // 2) flash-layout conversions (Q/K/V fp16)
    conv_qk<<<dim3(LSEQ / 64, B_ * HEADS_, 2), t>>>(qkv);
    conv_v<<<dim3((B_ * HID * LSEQ) / (256 * 4)), t>>>(qkv);

    // 3) flash attention (fp16 paths, 2 CTAs/SM)
    flash_mma<<<dim3(LSEQ / 128, B_ * HEADS_), t, FLASH_SMEM>>>(att);

    // 4) out = w_out @ att + b_out  (3-term bf16, fp32-grade)
    gemm_bf<<<dim3(LSEQ / 128, CDIM / 128, B_), t>>>(
        w_out, att, out, b_out, CDIM, LSEQ, HID,
        (long)HID * LSEQ, (long)CDIM * LSEQ);
}

// round 13
// speedup vs baseline: 2.5926x; 1.0675x over previous
#include <cuda_runtime.h>
#include <stdint.h>

#define B_     4
#define CDIM   512
#define LSEQ   2048
#define HEADS_ 8
#define DHEAD  64
#define HID    512
#define O3     1536
#define QSCALE 0.125f
#define LOG2E  1.44269504088896f

typedef uint32_t u32;

// ------------------------- scratch (device globals) -------------------------
__device__ float    g_att[(size_t)B_ * HID * LSEQ];   // [b][h*64+d][l]
__device__ uint16_t g_qh[(size_t)B_ * HEADS_ * LSEQ * DHEAD]; // [b][h][l][d] fp16 (q*log2e*scale)
__device__ uint16_t g_kh[(size_t)B_ * HEADS_ * LSEQ * DHEAD]; // fp16
__device__ uint16_t g_vh[(size_t)B_ * HEADS_ * DHEAD * LSEQ]; // [b][h][d][l] fp16

// ------------------------------- helpers -------------------------------------
__device__ __forceinline__ u32 smem_u32(const void* p) {
    u32 a; asm("{ .reg .u64 t; cvta.to.shared.u64 t, %1; cvt.u32.u64 %0, t; }"
               : "=r"(a) : "l"(p));
    return a;
}
__device__ __forceinline__ u32 pack_bf16x2(float a, float b) {   // lo=a, hi=b
    u32 r; asm("cvt.rn.bf16x2.f32 %0, %1, %2;" : "=r"(r) : "f"(b), "f"(a));
    return r;
}
__device__ __forceinline__ u32 pack_f16x2(float a, float b) {    // lo=a, hi=b
    u32 r; asm("cvt.rn.f16x2.f32 %0, %1, %2;" : "=r"(r) : "f"(b), "f"(a));
    return r;
}
__device__ __forceinline__ float ex2f(float x) {
    float y; asm("ex2.approx.f32 %0, %1;" : "=f"(y) : "f"(x)); return y;
}
__device__ __forceinline__ float bf_lo(u32 w) { return __uint_as_float(w << 16); }
__device__ __forceinline__ float bf_hi(u32 w) { return __uint_as_float(w & 0xffff0000u); }
__device__ __forceinline__ void split_pair(float a, float b, u32& hw, u32& lw) {
    hw = pack_bf16x2(a, b);
    lw = pack_bf16x2(a - bf_lo(hw), b - bf_hi(hw));
}
__device__ __forceinline__ void mma_bf(float c[4], const u32 a[4], u32 b0, u32 b1) {
    asm volatile(
        "mma.sync.aligned.m16n8k16.row.col.f32.bf16.bf16.f32 "
        "{%0,%1,%2,%3}, {%4,%5,%6,%7}, {%8,%9}, {%0,%1,%2,%3};"
        : "+f"(c[0]), "+f"(c[1]), "+f"(c[2]), "+f"(c[3])
        : "r"(a[0]), "r"(a[1]), "r"(a[2]), "r"(a[3]), "r"(b0), "r"(b1));
}
__device__ __forceinline__ void mma_fp(float c[4], const u32 a[4], u32 b0, u32 b1) {
    asm volatile(
        "mma.sync.aligned.m16n8k16.row.col.f32.f16.f16.f32 "
        "{%0,%1,%2,%3}, {%4,%5,%6,%7}, {%8,%9}, {%0,%1,%2,%3};"
        : "+f"(c[0]), "+f"(c[1]), "+f"(c[2]), "+f"(c[3])
        : "r"(a[0]), "r"(a[1]), "r"(a[2]), "r"(a[3]), "r"(b0), "r"(b1));
}
__device__ __forceinline__ void ldsm4(u32 r[4], u32 addr) {
    asm volatile("ldmatrix.sync.aligned.m8n8.x4.shared.b16 {%0,%1,%2,%3}, [%4];"
        : "=r"(r[0]), "=r"(r[1]), "=r"(r[2]), "=r"(r[3]) : "r"(addr));
}
__device__ __forceinline__ void ldsm4t(u32 r[4], u32 addr) {
    asm volatile("ldmatrix.sync.aligned.m8n8.x4.trans.shared.b16 {%0,%1,%2,%3}, [%4];"
        : "=r"(r[0]), "=r"(r[1]), "=r"(r[2]), "=r"(r[3]) : "r"(addr));
}

#define PKA 40
#define PNB 136

// ---------------------------------------------------------------------------
// qkv GEMM, single-term fp16, FUSED epilogue:
//   q/k tiles -> smem fp16 transpose -> g_qh/g_kh [b][h][l][d]
//   v tiles   -> direct fp16 [b][h][d][l]
// q rows pre-scaled by QSCALE*LOG2E (flash uses raw ex2).
// CTA 128(features) x 128(l), TK=32, 8 warps (4m x 2n).
// ---------------------------------------------------------------------------
#define QKV_SM 34816   // max(tiles 18944, transpose 128*136*2)

__global__ void __launch_bounds__(256, 2) gemm_qkv(
    const float* __restrict__ A, const float* __restrict__ Bm)
{
    __shared__ __align__(16) char smraw[QKV_SM];
    uint16_t* Ah = (uint16_t*)smraw;                 // [128][PKA]
    uint16_t* Bh = (uint16_t*)(smraw + 128 * PKA * 2); // [32][PNB]

    const int tid = threadIdx.x;
    const int lane = tid & 31, wid = tid >> 5;
    const int lam = lane & 3, g = lane >> 2;
    const int wm = (wid & 3) * 32, wn = (wid >> 2) * 64;
    const int m0 = blockIdx.y * 128, n0 = blockIdx.x * 128;
    const int bb = blockIdx.z;
    const float* Bb = Bm + (size_t)bb * CDIM * LSEQ;

    const int ar = tid >> 1, akb = (tid & 1) * 16;
    const int br = tid >> 3, bnb = (tid & 7) * 16;
    const int fr = lane & 15, fc = (lane >> 4) * 8;

    float acc[2][8][4];
#pragma unroll
    for (int mt = 0; mt < 2; mt++)
#pragma unroll
        for (int nt = 0; nt < 8; nt++)
#pragma unroll
            for (int r = 0; r < 4; r++) acc[mt][nt][r] = 0.f;

    for (int k0 = 0; k0 < CDIM; k0 += 32) {
        const float* Ag = A + (size_t)(m0 + ar) * CDIM + k0 + akb;
#pragma unroll
        for (int q = 0; q < 4; q++) {
            float4 v = *(const float4*)(Ag + q * 4);
            int kk = akb + q * 4;
            *(u32*)&Ah[ar * PKA + kk]     = pack_f16x2(v.x, v.y);
            *(u32*)&Ah[ar * PKA + kk + 2] = pack_f16x2(v.z, v.w);
        }
        const float* Bg = Bb + (size_t)(k0 + br) * LSEQ + n0 + bnb;
#pragma unroll
        for (int q = 0; q < 4; q++) {
            float4 v = *(const float4*)(Bg + q * 4);
            int nn = bnb + q * 4;
            *(u32*)&Bh[br * PNB + nn]     = pack_f16x2(v.x, v.y);
            *(u32*)&Bh[br * PNB + nn + 2] = pack_f16x2(v.z, v.w);
        }
        __syncthreads();

#pragma unroll
        for (int ks = 0; ks < 2; ks++) {
            u32 ahf[2][4];
#pragma unroll
            for (int mt = 0; mt < 2; mt++) {
                u32 off = (u32)((wm + mt * 16 + fr) * PKA + ks * 16 + fc) * 2;
                ldsm4(ahf[mt], smem_u32(Ah) + off);
            }
#pragma unroll
            for (int ntp = 0; ntp < 4; ntp++) {
                u32 bhf[4];
                u32 off = (u32)((ks * 16 + fr) * PNB + wn + ntp * 16 + fc) * 2;
                ldsm4t(bhf, smem_u32(Bh) + off);
#pragma unroll
                for (int mt = 0; mt < 2; mt++) {
                    mma_fp(acc[mt][2 * ntp],     ahf[mt], bhf[0], bhf[1]);
                    mma_fp(acc[mt][2 * ntp + 1], ahf[mt], bhf[2], bhf[3]);
                }
            }
        }
        __syncthreads();
    }

    if (m0 < 1024) {
        // ---- q/k tile: fp16 transpose via smem, then [b][h][l][d] rows
        const float sc = (m0 < 512) ? (QSCALE * LOG2E) : 1.0f;
        uint16_t* Ts = (uint16_t*)smraw;             // [n 128][m 128] pitch 136
#pragma unroll
        for (int mt = 0; mt < 2; mt++)
#pragma unroll
            for (int r = 0; r < 2; r++) {
                int ml = wm + mt * 16 + g + r * 8;
#pragma unroll
                for (int nt = 0; nt < 8; nt++) {
                    int nl = wn + nt * 8 + lam * 2;
                    u32 w = pack_f16x2(acc[mt][nt][r * 2] * sc,
                                       acc[mt][nt][r * 2 + 1] * sc);
                    Ts[nl * 136 + ml]       = (uint16_t)(w & 0xffffu);
                    Ts[(nl + 1) * 136 + ml] = (uint16_t)(w >> 16);
                }
            }
        __syncthreads();
        uint16_t* dstq = (m0 < 512) ? g_qh : g_kh;
        const int ob = m0 & 511;
#pragma unroll
        for (int it = tid; it < 2048; it += 256) {
            int nl = it >> 4, mc = (it & 15) * 8;
            int o = ob + mc;
            int h = o >> 6, d = o & 63;
            uint4 v = *(uint4*)&Ts[nl * 136 + mc];
            *(uint4*)(dstq + (((size_t)(bb * 8 + h) * LSEQ) + n0 + nl) * 64 + d) = v;
        }
    } else {
        // ---- v tile: direct fp16 [b][h][d][l]
        const int o0 = m0 - 1024;
#pragma unroll
        for (int mt = 0; mt < 2; mt++)
#pragma unroll
            for (int r = 0; r < 2; r++) {
                int o = o0 + wm + mt * 16 + g + r * 8;
                int h = o >> 6, d = o & 63;
                uint16_t* dv = g_vh + ((size_t)(bb * 8 + h) * 64 + d) * LSEQ + n0 + wn;
#pragma unroll
                for (int nt = 0; nt < 8; nt++)
                    *(u32*)(dv + nt * 8 + lam * 2) =
                        pack_f16x2(acc[mt][nt][r * 2], acc[mt][nt][r * 2 + 1]);
            }
    }
}

// ---------------------------------------------------------------------------
// bf16-split GEMM (3-term, fp32-grade) for the output projection.
// ---------------------------------------------------------------------------
__global__ void __launch_bounds__(256, 2) gemm_bf(
    const float* __restrict__ A, const float* __restrict__ Bm,
    float* __restrict__ C, const float* __restrict__ bias,
    int M, int N, int K, long strideB, long strideC)
{
    __shared__ uint16_t Ah[128 * PKA], Al[128 * PKA];
    __shared__ uint16_t Bh[32 * PNB],  Bl[32 * PNB];

    const int tid = threadIdx.x;
    const int lane = tid & 31, wid = tid >> 5;
    const int lam = lane & 3;
    const int wm = (wid & 3) * 32, wn = (wid >> 2) * 64;
    const int m0 = blockIdx.y * 128, n0 = blockIdx.x * 128;
    const float* Bb = Bm + (size_t)blockIdx.z * strideB;
    float* Cb = C + (size_t)blockIdx.z * strideC;

    const int ar = tid >> 1, akb = (tid & 1) * 16;
    const int br = tid >> 3, bnb = (tid & 7) * 16;
    const int fr = lane & 15, fc = (lane >> 4) * 8;

    float acc[2][8][4];
#pragma unroll
    for (int mt = 0; mt < 2; mt++)
#pragma unroll
        for (int nt = 0; nt < 8; nt++)
#pragma unroll
            for (int r = 0; r < 4; r++) acc[mt][nt][r] = 0.f;

    for (int k0 = 0; k0 < K; k0 += 32) {
        const float* Ag = A + (size_t)(m0 + ar) * K + k0 + akb;
#pragma unroll
        for (int q = 0; q < 4; q++) {
            float4 v = *(const float4*)(Ag + q * 4);
            u32 h0, l0, h1, l1;
            split_pair(v.x, v.y, h0, l0);
            split_pair(v.z, v.w, h1, l1);
            int kk = akb + q * 4;
            *(u32*)&Ah[ar * PKA + kk]     = h0;
            *(u32*)&Ah[ar * PKA + kk + 2] = h1;
            *(u32*)&Al[ar * PKA + kk]     = l0;
            *(u32*)&Al[ar * PKA + kk + 2] = l1;
        }
        const float* Bg = Bb + (size_t)(k0 + br) * N + n0 + bnb;
#pragma unroll
        for (int q = 0; q < 4; q++) {
            float4 v = *(const float4*)(Bg + q * 4);
            u32 h0, l0, h1, l1;
            split_pair(v.x, v.y, h0, l0);
            split_pair(v.z, v.w, h1, l1);
            int nn = bnb + q * 4;
            *(u32*)&Bh[br * PNB + nn]     = h0;
            *(u32*)&Bh[br * PNB + nn + 2] = h1;
            *(u32*)&Bl[br * PNB + nn]     = l0;
            *(u32*)&Bl[br * PNB + nn + 2] = l1;
        }
        __syncthreads();

#pragma unroll
        for (int ks = 0; ks < 2; ks++) {
            u32 ahf[2][4], alf[2][4];
#pragma unroll
            for (int mt = 0; mt < 2; mt++) {
                u32 off = (u32)((wm + mt * 16 + fr) * PKA + ks * 16 + fc) * 2;
                ldsm4(ahf[mt], smem_u32(Ah) + off);
                ldsm4(alf[mt], smem_u32(Al) + off);
            }
#pragma unroll
            for (int ntp = 0; ntp < 4; ntp++) {
                u32 bhf[4], blf[4];
                u32 off = (u32)((ks * 16 + fr) * PNB + wn + ntp * 16 + fc) * 2;
                ldsm4t(bhf, smem_u32(Bh) + off);
                ldsm4t(blf, smem_u32(Bl) + off);
#pragma unroll
                for (int mt = 0; mt < 2; mt++) {
                    mma_bf(acc[mt][2 * ntp],     ahf[mt], bhf[0], bhf[1]);
                    mma_bf(acc[mt][2 * ntp + 1], ahf[mt], bhf[2], bhf[3]);
                    mma_bf(acc[mt][2 * ntp],     ahf[mt], blf[0], blf[1]);
                    mma_bf(acc[mt][2 * ntp + 1], ahf[mt], blf[2], blf[3]);
                    mma_bf(acc[mt][2 * ntp],     alf[mt], bhf[0], bhf[1]);
                    mma_bf(acc[mt][2 * ntp + 1], alf[mt], bhf[2], bhf[3]);
                }
            }
        }
        __syncthreads();
    }

    const int g = lane >> 2;
#pragma unroll
    for (int mt = 0; mt < 2; mt++) {
#pragma unroll
        for (int r = 0; r < 2; r++) {
            int m = m0 + wm + mt * 16 + g + r * 8;
            float bv = bias ? bias[m] : 0.0f;
            float* Crow = Cb + (size_t)m * N + n0 + wn;
#pragma unroll
            for (int nt = 0; nt < 8; nt++) {
                float2 o;
                o.x = acc[mt][nt][r * 2 + 0] + bv;
                o.y = acc[mt][nt][r * 2 + 1] + bv;
                *(float2*)(Crow + nt * 8 + lam * 2) = o;
            }
        }
    }
}

// ---------------------------------------------------------------------------
// Flash attention v5: all-fp16 single-term, 64-key chunks, 2 CTAs/SM.
// q pre-scaled by log2e -> softmax via raw ex2 (no multiplies).
// ---------------------------------------------------------------------------
#define PD  72
#define POT 132

#define F_QH 0
#define F_KH (128 * PD * 2)
#define F_V  (F_KH + 64 * PD * 2)
#define FLASH_SMEM (F_V + 64 * PD * 2)   // 36864 B

__global__ void __launch_bounds__(256, 2) flash_mma(float* __restrict__ att)
{
    extern __shared__ char smc[];
    uint16_t* Qh = (uint16_t*)(smc + F_QH);
    uint16_t* Kh = (uint16_t*)(smc + F_KH);
    uint16_t* Vs = (uint16_t*)(smc + F_V);

    const int tid = threadIdx.x;
    const int lane = tid & 31, wid = tid >> 5;
    const int g = lane >> 2, lam = lane & 3;
    const int fr = lane & 15, fc = (lane >> 4) * 8;
    const int bh = blockIdx.y;
    const int q0 = blockIdx.x * 128;

    const uint16_t* kh = g_kh + (size_t)bh * LSEQ * DHEAD;
    const uint16_t* vh = g_vh + (size_t)bh * DHEAD * LSEQ;

    {
        const uint16_t* qh = g_qh + ((size_t)bh * LSEQ + q0) * DHEAD;
#pragma unroll
        for (int it = tid; it < 1024; it += 256) {
            int r = it >> 3, c = (it & 7) * 8;
            *(uint4*)&Qh[r * PD + c] = *(const uint4*)(qh + (size_t)r * 64 + c);
        }
    }

    float o[8][4];
#pragma unroll
    for (int nt = 0; nt < 8; nt++)
#pragma unroll
        for (int r = 0; r < 4; r++) o[nt][r] = 0.f;
    float rs0 = 0.f, rs1 = 0.f;

    const u32 qB = smem_u32(Qh), kB = smem_u32(Kh), vB = smem_u32(Vs);

    for (int n0 = 0; n0 < LSEQ; n0 += 64) {
        __syncthreads();
#pragma unroll
        for (int it = tid; it < 512; it += 256) {
            int r = it >> 3, c = (it & 7) * 8;
            *(uint4*)&Kh[r * PD + c] =
                *(const uint4*)(kh + (size_t)(n0 + r) * 64 + c);
            *(uint4*)&Vs[r * PD + c] =
                *(const uint4*)(vh + (size_t)r * LSEQ + n0 + c);
        }
        __syncthreads();

        float s[8][4];
#pragma unroll
        for (int nt = 0; nt < 8; nt++)
#pragma unroll
            for (int r = 0; r < 4; r++) s[nt][r] = 0.f;

#pragma unroll
        for (int ks = 0; ks < 4; ks++) {
            u32 qf[4];
            u32 qoff = (u32)((wid * 16 + fr) * PD + ks * 16 + fc) * 2;
            ldsm4(qf, qB + qoff);
#pragma unroll
            for (int ntp = 0; ntp < 4; ntp++) {
                u32 kf[4];
                u32 koff = (u32)((ntp * 16 + fr) * PD + ks * 16 + fc) * 2;
                ldsm4(kf, kB + koff);
                mma_fp(s[2 * ntp],     qf, kf[0], kf[2]);
                mma_fp(s[2 * ntp + 1], qf, kf[1], kf[3]);
            }
        }

        // exp2 (q pre-scaled by log2e): no multiplies
#pragma unroll
        for (int nt = 0; nt < 8; nt++) {
            s[nt][0] = ex2f(s[nt][0]);
            s[nt][1] = ex2f(s[nt][1]);
            s[nt][2] = ex2f(s[nt][2]);
            s[nt][3] = ex2f(s[nt][3]);
            rs0 += s[nt][0] + s[nt][1];
            rs1 += s[nt][2] + s[nt][3];
        }

#pragma unroll
        for (int ks2 = 0; ks2 < 4; ks2++) {
            int t = ks2 * 2;
            u32 pa[4];
            pa[0] = pack_f16x2(s[t][0],     s[t][1]);
            pa[1] = pack_f16x2(s[t][2],     s[t][3]);
            pa[2] = pack_f16x2(s[t + 1][0], s[t + 1][1]);
            pa[3] = pack_f16x2(s[t + 1][2], s[t + 1][3]);
#pragma unroll
            for (int dp = 0; dp < 4; dp++) {
                u32 vf[4];
                u32 voff = (u32)((dp * 16 + fr) * PD + ks2 * 16 + fc) * 2;
                ldsm4(vf, vB + voff);
                mma_fp(o[2 * dp],     pa, vf[0], vf[2]);
                mma_fp(o[2 * dp + 1], pa, vf[1], vf[3]);
            }
        }
    }

    rs0 += __shfl_xor_sync(0xffffffffu, rs0, 1);
    rs0 += __shfl_xor_sync(0xffffffffu, rs0, 2);
    rs1 += __shfl_xor_sync(0xffffffffu, rs1, 1);
    rs1 += __shfl_xor_sync(0xffffffffu, rs1, 2);
    const float inv0 = 1.0f / rs0, inv1 = 1.0f / rs1;

    float* Ot = (float*)smc;
    __syncthreads();
#pragma unroll
    for (int nt = 0; nt < 8; nt++) {
        int d = nt * 8 + 2 * lam;
        int q = wid * 16 + g;
        Ot[d * POT + q]           = o[nt][0] * inv0;
        Ot[(d + 1) * POT + q]     = o[nt][1] * inv0;
        Ot[d * POT + q + 8]       = o[nt][2] * inv1;
        Ot[(d + 1) * POT + q + 8] = o[nt][3] * inv1;
    }
    __syncthreads();
    const int b = bh >> 3, h = bh & 7;
    float* dst = att + ((size_t)b * HID + h * DHEAD) * LSEQ + q0;
#pragma unroll
    for (int it = tid; it < 2048; it += 256) {
        int d = it >> 5, c = (it & 31) * 4;
        *(float4*)(dst + (size_t)d * LSEQ + c) = *(float4*)&Ot[d * POT + c];
    }
}

// ---------------------------------------------------------------------------
extern "C" void kernel_launch(void* const* d_in, const int* in_sizes, int n_in,
                              void* d_out, int out_size)
{
    const float* x     = (const float*)d_in[0];
    const float* w_qkv = (const float*)d_in[1];
    const float* w_out = (const float*)d_in[2];
    const float* b_out = (const float*)d_in[3];
    float* out = (float*)d_out;

    float* att;
    cudaGetSymbolAddress((void**)&att, g_att);

    cudaFuncSetAttribute(flash_mma,
        cudaFuncAttributeMaxDynamicSharedMemorySize, FLASH_SMEM);

    dim3 t(256);
    // 1) fused qkv projection + fp16 layout conversion (q pre-scaled w/ log2e)
    gemm_qkv<<<dim3(LSEQ / 128, O3 / 128, B_), t>>>(w_qkv, x);

    // 2) flash attention (fp16 paths, ex2 softmax, 2 CTAs/SM)
    flash_mma<<<dim3(LSEQ / 128, B_ * HEADS_), t, FLASH_SMEM>>>(att);

    // 3) out = w_out @ att + b_out  (3-term bf16, fp32-grade)
    gemm_bf<<<dim3(LSEQ / 128, CDIM / 128, B_), t>>>(
        w_out, att, out, b_out, CDIM, LSEQ, HID,
        (long)HID * LSEQ, (long)CDIM * LSEQ);
}